// round 1
// baseline (speedup 1.0000x reference)
#include <cuda_runtime.h>
#include <math.h>
#include <stdint.h>

#define B_ 2
#define T_ 2048
#define C_ 1024
#define H_ 16
#define HD_ 64
#define M_ 256
#define S_ (T_ + 2*M_)   /* 2560 */
#define KC_ 4

// ---------------- scratch (static device globals; no runtime alloc) -------
__device__ float g_xcat[B_*S_*C_];   // concat(x, fwd_mem, rev_mem) per batch
__device__ float g_q  [B_*T_*C_];
__device__ float g_k  [B_*S_*C_];
__device__ float g_v  [B_*S_*C_];
__device__ float g_gate[B_*T_*H_];
__device__ float g_attn[B_*T_*C_];
__device__ float g_z  [B_*T_*C_];

// ---------------- pack: xcat[b, 0:T)=x, [T:T+M)=fwd, [T+M:S)=rev ----------
__global__ void pack_kernel(const float4* __restrict__ x,
                            const float4* __restrict__ fwd,
                            const float4* __restrict__ rev,
                            float4* __restrict__ xc) {
    const int C4 = C_/4;
    int idx = blockIdx.x * 256 + threadIdx.x;
    if (idx >= B_*S_*C4) return;
    int c4 = idx % C4;
    int r  = (idx / C4) % S_;
    int b  = idx / (C4 * S_);
    float4 val;
    if (r < T_)            val = x  [(b*T_ + r)          * C4 + c4];
    else if (r < T_ + M_)  val = fwd[(b*M_ + (r - T_))   * C4 + c4];
    else                   val = rev[(b*M_ + (r - T_-M_))* C4 + c4];
    xc[idx] = val;
}

// ---------------- SGEMM NT: C[m,n] = sum_k A[m,k] * B[n,k] ---------------
// 128x128 tile, BK=8, 256 threads, 8x8 per thread. Mr,Nr,Kr multiples of 128/8.
__global__ __launch_bounds__(256)
void sgemm_nt(const float* __restrict__ A, const float* __restrict__ Bm,
              float* __restrict__ Cm, int Mr, int Nr, int Kr) {
    __shared__ float As[8][128];
    __shared__ float Bs[8][128];
    const int tid = threadIdx.x;
    const int tx = tid & 15, ty = tid >> 4;
    const int m0 = blockIdx.y * 128, n0 = blockIdx.x * 128;
    const int lr = tid >> 1;          // row within tile 0..127
    const int lk = (tid & 1) * 4;     // k offset 0 or 4

    float acc[8][8];
    #pragma unroll
    for (int i = 0; i < 8; i++)
        #pragma unroll
        for (int j = 0; j < 8; j++) acc[i][j] = 0.f;

    const float* Aptr = A  + (size_t)(m0 + lr) * Kr + lk;
    const float* Bptr = Bm + (size_t)(n0 + lr) * Kr + lk;

    for (int k0 = 0; k0 < Kr; k0 += 8) {
        float4 av = *(const float4*)(Aptr + k0);
        float4 bv = *(const float4*)(Bptr + k0);
        As[lk+0][lr] = av.x; As[lk+1][lr] = av.y;
        As[lk+2][lr] = av.z; As[lk+3][lr] = av.w;
        Bs[lk+0][lr] = bv.x; Bs[lk+1][lr] = bv.y;
        Bs[lk+2][lr] = bv.z; Bs[lk+3][lr] = bv.w;
        __syncthreads();
        #pragma unroll
        for (int k = 0; k < 8; k++) {
            float a[8], b[8];
            *(float4*)(a)   = *(const float4*)&As[k][ty*8];
            *(float4*)(a+4) = *(const float4*)&As[k][ty*8+4];
            *(float4*)(b)   = *(const float4*)&Bs[k][tx*8];
            *(float4*)(b+4) = *(const float4*)&Bs[k][tx*8+4];
            #pragma unroll
            for (int i = 0; i < 8; i++)
                #pragma unroll
                for (int j = 0; j < 8; j++)
                    acc[i][j] += a[i] * b[j];
        }
        __syncthreads();
    }
    #pragma unroll
    for (int i = 0; i < 8; i++) {
        float* cp = Cm + (size_t)(m0 + ty*8 + i) * Nr + n0 + tx*8;
        float4 v0 = make_float4(acc[i][0], acc[i][1], acc[i][2], acc[i][3]);
        float4 v1 = make_float4(acc[i][4], acc[i][5], acc[i][6], acc[i][7]);
        *(float4*)(cp)     = v0;
        *(float4*)(cp + 4) = v1;
    }
}

// ---------------- gate: g[b,t,h] = sigmoid(q[b,t,:] . gate_w[h,:] + b[h]) -
__global__ __launch_bounds__(256)
void gate_kernel(const float* __restrict__ q, const float* __restrict__ gw,
                 const float* __restrict__ gb, float* __restrict__ gate) {
    __shared__ float qrow[C_];
    const int bt = blockIdx.x;                     // 0..B*T-1
    for (int c = threadIdx.x; c < C_; c += 256)
        qrow[c] = q[(size_t)bt * C_ + c];
    __syncthreads();
    const int warp = threadIdx.x >> 5, lane = threadIdx.x & 31;
    for (int h = warp; h < H_; h += 8) {
        float s = 0.f;
        for (int c = lane; c < C_; c += 32)
            s += qrow[c] * gw[h * C_ + c];
        #pragma unroll
        for (int o = 16; o; o >>= 1) s += __shfl_xor_sync(0xffffffffu, s, o);
        if (lane == 0)
            gate[(size_t)bt * H_ + h] = 1.f / (1.f + __expf(-(s + gb[h])));
    }
}

// ---------------- flash attention with gated memory branch ----------------
// Grid: (T/64, B*H). Block 256. Dynamic smem:
//   Qs[64][68] | KV[64][68] (K^T then V) | P[64][68] | rowm/rowl/rowf/gsm[64]
#define APAD 68
#define ATT_SMEM ((3*64*APAD + 4*64) * (int)sizeof(float))

__global__ __launch_bounds__(256)
void attn_kernel(const float* __restrict__ q, const float* __restrict__ k,
                 const float* __restrict__ v, const float* __restrict__ gate,
                 float* __restrict__ outp) {
    extern __shared__ float sm[];
    float* Qs   = sm;
    float* KV   = sm + 64*APAD;
    float* P    = sm + 2*64*APAD;
    float* rowm = sm + 3*64*APAD;
    float* rowl = rowm + 64;
    float* rowf = rowl + 64;
    float* gsm  = rowf + 64;

    const int tid = threadIdx.x;
    const int tx = tid & 15, ty = tid >> 4;
    const int b  = blockIdx.y >> 4;
    const int h  = blockIdx.y & 15;
    const int t0 = (gridDim.x - 1 - blockIdx.x) * 64;  // heavy tiles first
    const float scale = 0.125f;

    // load Q tile [64 rows x 64 dims]
    {
        int r  = tid >> 2;
        int c0 = (tid & 3) * 16;
        const float* src = q + (size_t)(b*T_ + t0 + r) * C_ + h*HD_ + c0;
        #pragma unroll
        for (int u = 0; u < 4; u++)
            *(float4*)&Qs[r*APAD + c0 + u*4] = *(const float4*)(src + u*4);
    }
    if (tid < 64) {
        rowm[tid] = -1e30f;
        rowl[tid] = 0.f;
        gsm[tid]  = gate[(size_t)(b*T_ + t0 + tid) * H_ + h];
    }

    float acc1[4][4], acc2[4][4];
    #pragma unroll
    for (int i = 0; i < 4; i++)
        #pragma unroll
        for (int j = 0; j < 4; j++) { acc1[i][j] = 0.f; acc2[i][j] = 0.f; }

    const int nChunk = t0/64 + 1;          // causal: only tiles with s0 <= t0
    const int nTiles = nChunk + (2*M_)/64; // + 8 memory tiles

    for (int it = 0; it < nTiles; it++) {
        const bool isMem  = (it >= nChunk);
        const int  s0     = isMem ? (T_ + (it - nChunk)*64) : it*64;
        const bool isDiag = (!isMem) && (s0 == t0);

        __syncthreads();   // prev PV done reading KV; P free
        // load K transposed: KV[d][j]
        {
            int r  = tid >> 2;          // key row j
            int c0 = (tid & 3) * 16;    // d base
            const float* src = k + (size_t)(b*S_ + s0 + r) * C_ + h*HD_ + c0;
            #pragma unroll
            for (int u = 0; u < 16; u++)
                KV[(c0 + u)*APAD + r] = src[u];
        }
        __syncthreads();

        // scores: sc[i][j] = sum_d Q[i,d] * K[j,d]
        float sc[4][4];
        #pragma unroll
        for (int i = 0; i < 4; i++)
            #pragma unroll
            for (int j = 0; j < 4; j++) sc[i][j] = 0.f;
        #pragma unroll 4
        for (int d = 0; d < 64; d++) {
            float aq[4];
            #pragma unroll
            for (int ii = 0; ii < 4; ii++) aq[ii] = Qs[(ty*4+ii)*APAD + d];
            float4 bk = *(const float4*)&KV[d*APAD + (tx<<2)];
            #pragma unroll
            for (int ii = 0; ii < 4; ii++) {
                sc[ii][0] += aq[ii]*bk.x; sc[ii][1] += aq[ii]*bk.y;
                sc[ii][2] += aq[ii]*bk.z; sc[ii][3] += aq[ii]*bk.w;
            }
        }
        // scale + causal mask (diagonal tile only), stage to P
        #pragma unroll
        for (int ii = 0; ii < 4; ii++) {
            int trow = t0 + ty*4 + ii;
            float4 w;
            float vv0 = sc[ii][0]*scale, vv1 = sc[ii][1]*scale;
            float vv2 = sc[ii][2]*scale, vv3 = sc[ii][3]*scale;
            if (isDiag) {
                int sbase = s0 + (tx<<2);
                if (sbase + 0 > trow) vv0 = -1e30f;
                if (sbase + 1 > trow) vv1 = -1e30f;
                if (sbase + 2 > trow) vv2 = -1e30f;
                if (sbase + 3 > trow) vv3 = -1e30f;
            }
            w.x = vv0; w.y = vv1; w.z = vv2; w.w = vv3;
            *(float4*)&P[(ty*4+ii)*APAD + (tx<<2)] = w;
        }
        __syncthreads();

        // load V into KV: KV[j][d]  (K no longer needed)
        {
            int r  = tid >> 2;
            int c0 = (tid & 3) * 16;
            const float* src = v + (size_t)(b*S_ + s0 + r) * C_ + h*HD_ + c0;
            #pragma unroll
            for (int u = 0; u < 4; u++)
                *(float4*)&KV[r*APAD + c0 + u*4] = *(const float4*)(src + u*4);
        }
        // row max + rescale factor
        if (tid < 64) {
            float mx = -1e30f;
            #pragma unroll 8
            for (int c = 0; c < 64; c++) mx = fmaxf(mx, P[tid*APAD + c]);
            float mold = rowm[tid];
            float mnew = fmaxf(mold, mx);
            rowf[tid] = __expf(mold - mnew);
            rowm[tid] = mnew;
        }
        __syncthreads();

        // exponentiate in place + rescale accumulators
        #pragma unroll
        for (int ii = 0; ii < 4; ii++) {
            int r = ty*4 + ii;
            float mr = rowm[r];
            float fr = rowf[r];
            float* pp = &P[r*APAD + (tx<<2)];
            float4 pv = *(float4*)pp;
            pv.x = __expf(pv.x - mr); pv.y = __expf(pv.y - mr);
            pv.z = __expf(pv.z - mr); pv.w = __expf(pv.w - mr);
            *(float4*)pp = pv;
            #pragma unroll
            for (int jj = 0; jj < 4; jj++) { acc1[ii][jj] *= fr; acc2[ii][jj] *= fr; }
        }
        __syncthreads();

        // row sum (P unchanged by this; PV can proceed in same phase)
        if (tid < 64) {
            float s = 0.f;
            #pragma unroll 8
            for (int c = 0; c < 64; c++) s += P[tid*APAD + c];
            rowl[tid] = rowl[tid] * rowf[tid] + s;
        }

        // PV: acc[i][d] += P[i][j] * V[j][d]
#define PV_LOOP(ACC)                                                        \
        _Pragma("unroll 4")                                                 \
        for (int j = 0; j < 64; j++) {                                      \
            float4 vv = *(const float4*)&KV[j*APAD + (tx<<2)];              \
            float pq[4];                                                    \
            _Pragma("unroll")                                               \
            for (int ii = 0; ii < 4; ii++) pq[ii] = P[(ty*4+ii)*APAD + j];  \
            _Pragma("unroll")                                               \
            for (int ii = 0; ii < 4; ii++) {                                \
                ACC[ii][0] += pq[ii]*vv.x; ACC[ii][1] += pq[ii]*vv.y;       \
                ACC[ii][2] += pq[ii]*vv.z; ACC[ii][3] += pq[ii]*vv.w;       \
            }                                                               \
        }
        if (!isMem) { PV_LOOP(acc1) } else { PV_LOOP(acc2) }
#undef PV_LOOP
    }
    __syncthreads();

    // epilogue: Y = (acc_chunk + g * acc_mem) / l
    #pragma unroll
    for (int ii = 0; ii < 4; ii++) {
        int r = ty*4 + ii;
        float inv = 1.f / rowl[r];
        float gg  = gsm[r];
        float4 o;
        o.x = (acc1[ii][0] + gg*acc2[ii][0]) * inv;
        o.y = (acc1[ii][1] + gg*acc2[ii][1]) * inv;
        o.z = (acc1[ii][2] + gg*acc2[ii][2]) * inv;
        o.w = (acc1[ii][3] + gg*acc2[ii][3]) * inv;
        *(float4*)&outp[(size_t)(b*T_ + t0 + r) * C_ + h*HD_ + (tx<<2)] = o;
    }
}

// ---------------- canon conv: z = y + depthwise_causal_conv(y) + bias -----
__global__ __launch_bounds__(256)
void conv_kernel(const float* __restrict__ y, const float* __restrict__ cw,
                 const float* __restrict__ cb, float* __restrict__ z) {
    int idx = blockIdx.x * 256 + threadIdx.x;
    if (idx >= B_*T_*C_) return;
    int c = idx % C_;
    int t = (idx / C_) % T_;
    int b = idx / (C_ * T_);
    float s = y[idx] + cb[c];
    #pragma unroll
    for (int j = 0; j < KC_; j++) {
        int tt = t - (KC_ - 1) + j;
        if (tt >= 0)
            s += y[((size_t)(b*T_ + tt)) * C_ + c] * cw[c*KC_ + j];
    }
    z[idx] = s;
}

// ---------------- orchestration -------------------------------------------
extern "C" void kernel_launch(void* const* d_in, const int* in_sizes, int n_in,
                              void* d_out, int out_size) {
    const float* x   = (const float*)d_in[0];
    const float* fwd = (const float*)d_in[1];
    const float* rev = (const float*)d_in[2];
    const float* Wq  = (const float*)d_in[3];
    const float* Wk  = (const float*)d_in[4];
    const float* Wv  = (const float*)d_in[5];
    const float* Wo  = (const float*)d_in[6];
    const float* gw  = (const float*)d_in[7];
    const float* gb  = (const float*)d_in[8];
    const float* cw  = (const float*)d_in[9];
    const float* cb  = (const float*)d_in[10];
    float* out = (float*)d_out;

    float *xc, *qb, *kb, *vb, *gt, *at, *zb;
    cudaGetSymbolAddress((void**)&xc, g_xcat);
    cudaGetSymbolAddress((void**)&qb, g_q);
    cudaGetSymbolAddress((void**)&kb, g_k);
    cudaGetSymbolAddress((void**)&vb, g_v);
    cudaGetSymbolAddress((void**)&gt, g_gate);
    cudaGetSymbolAddress((void**)&at, g_attn);
    cudaGetSymbolAddress((void**)&zb, g_z);

    cudaFuncSetAttribute(attn_kernel,
                         cudaFuncAttributeMaxDynamicSharedMemorySize, ATT_SMEM);

    // 1. pack concat(x, fwd, rev)
    {
        int n4 = B_*S_*(C_/4);
        pack_kernel<<<(n4 + 255)/256, 256>>>((const float4*)x, (const float4*)fwd,
                                             (const float4*)rev, (float4*)xc);
    }
    // 2. projections (NT gemms: out[m,n] = in[m,:] . W[n,:])
    sgemm_nt<<<dim3(C_/128, (B_*T_)/128), 256>>>(x,  Wq, qb, B_*T_, C_, C_);
    sgemm_nt<<<dim3(C_/128, (B_*S_)/128), 256>>>(xc, Wk, kb, B_*S_, C_, C_);
    sgemm_nt<<<dim3(C_/128, (B_*S_)/128), 256>>>(xc, Wv, vb, B_*S_, C_, C_);
    // 3. gate (needs q)
    gate_kernel<<<B_*T_, 256>>>(qb, gw, gb, gt);
    // 4. attention
    attn_kernel<<<dim3(T_/64, B_*H_), 256, ATT_SMEM>>>(qb, kb, vb, gt, at);
    // 5. canon conv
    conv_kernel<<<(B_*T_*C_ + 255)/256, 256>>>(at, cw, cb, zb);
    // 6. output projection straight into d_out
    sgemm_nt<<<dim3(C_/128, (B_*T_)/128), 256>>>(zb, Wo, out, B_*T_, C_, C_);
}

// round 2
// speedup vs baseline: 1.5339x; 1.5339x over previous
#include <cuda_runtime.h>
#include <math.h>
#include <stdint.h>

#define B_ 2
#define T_ 2048
#define C_ 1024
#define H_ 16
#define HD_ 64
#define M_ 256
#define S_ (T_ + 2*M_)   /* 2560 */
#define KC_ 4

// ---------------- scratch (static device globals; no runtime alloc) -------
__device__ float g_xcat[B_*S_*C_];   // concat(x, fwd_mem, rev_mem) per batch
__device__ float g_q  [B_*T_*C_];
__device__ float g_k  [B_*S_*C_];
__device__ float g_v  [B_*S_*C_];
__device__ float g_gate[B_*T_*H_];
__device__ float g_attn[B_*T_*C_];
__device__ float g_z  [B_*T_*C_];

// ---------------- pack: xcat[b, 0:T)=x, [T:T+M)=fwd, [T+M:S)=rev ----------
__global__ void pack_kernel(const float4* __restrict__ x,
                            const float4* __restrict__ fwd,
                            const float4* __restrict__ rev,
                            float4* __restrict__ xc) {
    const int C4 = C_/4;
    int idx = blockIdx.x * 256 + threadIdx.x;
    if (idx >= B_*S_*C4) return;
    int c4 = idx % C4;
    int r  = (idx / C4) % S_;
    int b  = idx / (C4 * S_);
    float4 val;
    if (r < T_)            val = x  [(b*T_ + r)          * C4 + c4];
    else if (r < T_ + M_)  val = fwd[(b*M_ + (r - T_))   * C4 + c4];
    else                   val = rev[(b*M_ + (r - T_-M_))* C4 + c4];
    xc[idx] = val;
}

// ================= TF32 tensor-core GEMM (NT) ==============================
// C[m,n] = sum_k A[m,k] * B[n,k].  Tiles: BM=BN=128, BK=32. 256 threads,
// 8 warps in 2(M) x 4(N); each warp owns 64x32 via m16n8k8 tf32 mma.sync.
// Double-buffered dynamic smem, padded stride 36 words (conflict-free).

#define GBM 128
#define GBN 128
#define GBK 32
#define GPAD 36
#define GEMM_SMEM (2 * (GBM + GBN) * GPAD * (int)sizeof(uint32_t))  // 73728 B

__device__ __forceinline__ uint32_t f2tf32(float f) {
    uint32_t r;
    asm("cvt.rna.tf32.f32 %0, %1;" : "=r"(r) : "f"(f));
    return r;
}

__device__ __forceinline__ void mma_tf32(float* d, const uint32_t* a,
                                         const uint32_t* b) {
    asm volatile(
        "mma.sync.aligned.m16n8k8.row.col.f32.tf32.tf32.f32 "
        "{%0,%1,%2,%3}, {%4,%5,%6,%7}, {%8,%9}, {%0,%1,%2,%3};"
        : "+f"(d[0]), "+f"(d[1]), "+f"(d[2]), "+f"(d[3])
        : "r"(a[0]), "r"(a[1]), "r"(a[2]), "r"(a[3]),
          "r"(b[0]), "r"(b[1]));
}

__global__ __launch_bounds__(256)
void gemm_tf32(const float* __restrict__ A, const float* __restrict__ Bm,
               float* __restrict__ Cm, int Mr, int Nr, int Kr) {
    extern __shared__ uint32_t smtf[];
    uint32_t* As = smtf;                       // [2][GBM*GPAD]
    uint32_t* Bs = smtf + 2 * GBM * GPAD;      // [2][GBN*GPAD]

    const int tid  = threadIdx.x;
    const int lane = tid & 31, warp = tid >> 5;
    const int g = lane >> 2, qc = lane & 3;
    const int wm0 = (warp >> 2) * 64;
    const int wn0 = (warp & 3) * 32;
    const int m0 = blockIdx.y * GBM, n0 = blockIdx.x * GBN;

    const int ldr = tid >> 1;              // 0..127: tile row loaded
    const int ldc = (tid & 1) * 16;        // k offset 0 or 16
    const float* Ag = A  + (size_t)(m0 + ldr) * Kr + ldc;
    const float* Bg = Bm + (size_t)(n0 + ldr) * Kr + ldc;

    float acc[4][4][4] = {};

    float4 ra[4], rb[4];
    #pragma unroll
    for (int u = 0; u < 4; u++) {
        ra[u] = *(const float4*)(Ag + u*4);
        rb[u] = *(const float4*)(Bg + u*4);
    }
    // store stage 0
    {
        uint32_t* as = As + ldr * GPAD + ldc;
        uint32_t* bs = Bs + ldr * GPAD + ldc;
        #pragma unroll
        for (int u = 0; u < 4; u++) {
            uint4 ua = make_uint4(f2tf32(ra[u].x), f2tf32(ra[u].y),
                                  f2tf32(ra[u].z), f2tf32(ra[u].w));
            uint4 ub = make_uint4(f2tf32(rb[u].x), f2tf32(rb[u].y),
                                  f2tf32(rb[u].z), f2tf32(rb[u].w));
            *(uint4*)(as + u*4) = ua;
            *(uint4*)(bs + u*4) = ub;
        }
    }
    __syncthreads();

    const int nk = Kr / GBK;
    for (int kt = 0; kt < nk; kt++) {
        const int cur = kt & 1;
        if (kt + 1 < nk) {
            const float* Ap = Ag + (size_t)(kt + 1) * GBK;
            const float* Bp = Bg + (size_t)(kt + 1) * GBK;
            #pragma unroll
            for (int u = 0; u < 4; u++) {
                ra[u] = *(const float4*)(Ap + u*4);
                rb[u] = *(const float4*)(Bp + u*4);
            }
        }
        const uint32_t* as = As + cur * GBM * GPAD;
        const uint32_t* bs = Bs + cur * GBN * GPAD;
        #pragma unroll
        for (int kp = 0; kp < 4; kp++) {
            const int k0 = kp * 8;
            uint32_t af[4][4], bf[4][2];
            #pragma unroll
            for (int mt = 0; mt < 4; mt++) {
                int r = wm0 + mt*16 + g;
                af[mt][0] = as[(size_t)r      * GPAD + k0 + qc];
                af[mt][1] = as[(size_t)(r+8)  * GPAD + k0 + qc];
                af[mt][2] = as[(size_t)r      * GPAD + k0 + qc + 4];
                af[mt][3] = as[(size_t)(r+8)  * GPAD + k0 + qc + 4];
            }
            #pragma unroll
            for (int nt = 0; nt < 4; nt++) {
                int r = wn0 + nt*8 + g;
                bf[nt][0] = bs[(size_t)r * GPAD + k0 + qc];
                bf[nt][1] = bs[(size_t)r * GPAD + k0 + qc + 4];
            }
            #pragma unroll
            for (int mt = 0; mt < 4; mt++)
                #pragma unroll
                for (int nt = 0; nt < 4; nt++)
                    mma_tf32(acc[mt][nt], af[mt], bf[nt]);
        }
        if (kt + 1 < nk) {
            __syncthreads();
            uint32_t* asn = As + (cur ^ 1) * GBM * GPAD + ldr * GPAD + ldc;
            uint32_t* bsn = Bs + (cur ^ 1) * GBN * GPAD + ldr * GPAD + ldc;
            #pragma unroll
            for (int u = 0; u < 4; u++) {
                uint4 ua = make_uint4(f2tf32(ra[u].x), f2tf32(ra[u].y),
                                      f2tf32(ra[u].z), f2tf32(ra[u].w));
                uint4 ub = make_uint4(f2tf32(rb[u].x), f2tf32(rb[u].y),
                                      f2tf32(rb[u].z), f2tf32(rb[u].w));
                *(uint4*)(asn + u*4) = ua;
                *(uint4*)(bsn + u*4) = ub;
            }
            __syncthreads();
        }
    }

    // epilogue: d0:(g,2qc) d1:(g,2qc+1) d2:(g+8,2qc) d3:(g+8,2qc+1)
    #pragma unroll
    for (int mt = 0; mt < 4; mt++) {
        #pragma unroll
        for (int nt = 0; nt < 4; nt++) {
            int row = m0 + wm0 + mt*16 + g;
            int col = n0 + wn0 + nt*8 + qc*2;
            float2 lo = make_float2(acc[mt][nt][0], acc[mt][nt][1]);
            float2 hi = make_float2(acc[mt][nt][2], acc[mt][nt][3]);
            *(float2*)(Cm + (size_t)row     * Nr + col) = lo;
            *(float2*)(Cm + (size_t)(row+8) * Nr + col) = hi;
        }
    }
}

// ---------------- gate: g[b,t,h] = sigmoid(q[b,t,:] . gate_w[h,:] + b[h]) -
__global__ __launch_bounds__(256)
void gate_kernel(const float* __restrict__ q, const float* __restrict__ gw,
                 const float* __restrict__ gb, float* __restrict__ gate) {
    __shared__ float qrow[C_];
    const int bt = blockIdx.x;                     // 0..B*T-1
    for (int c = threadIdx.x; c < C_; c += 256)
        qrow[c] = q[(size_t)bt * C_ + c];
    __syncthreads();
    const int warp = threadIdx.x >> 5, lane = threadIdx.x & 31;
    for (int h = warp; h < H_; h += 8) {
        float s = 0.f;
        for (int c = lane; c < C_; c += 32)
            s += qrow[c] * gw[h * C_ + c];
        #pragma unroll
        for (int o = 16; o; o >>= 1) s += __shfl_xor_sync(0xffffffffu, s, o);
        if (lane == 0)
            gate[(size_t)bt * H_ + h] = 1.f / (1.f + __expf(-(s + gb[h])));
    }
}

// ---------------- flash attention with gated memory branch ----------------
#define APAD 68
#define ATT_SMEM ((3*64*APAD + 4*64) * (int)sizeof(float))

__global__ __launch_bounds__(256)
void attn_kernel(const float* __restrict__ q, const float* __restrict__ k,
                 const float* __restrict__ v, const float* __restrict__ gate,
                 float* __restrict__ outp) {
    extern __shared__ float sm[];
    float* Qs   = sm;
    float* KV   = sm + 64*APAD;
    float* P    = sm + 2*64*APAD;
    float* rowm = sm + 3*64*APAD;
    float* rowl = rowm + 64;
    float* rowf = rowl + 64;
    float* gsm  = rowf + 64;

    const int tid = threadIdx.x;
    const int tx = tid & 15, ty = tid >> 4;
    const int b  = blockIdx.y >> 4;
    const int h  = blockIdx.y & 15;
    const int t0 = (gridDim.x - 1 - blockIdx.x) * 64;  // heavy tiles first
    const float scale = 0.125f;

    {
        int r  = tid >> 2;
        int c0 = (tid & 3) * 16;
        const float* src = q + (size_t)(b*T_ + t0 + r) * C_ + h*HD_ + c0;
        #pragma unroll
        for (int u = 0; u < 4; u++)
            *(float4*)&Qs[r*APAD + c0 + u*4] = *(const float4*)(src + u*4);
    }
    if (tid < 64) {
        rowm[tid] = -1e30f;
        rowl[tid] = 0.f;
        gsm[tid]  = gate[(size_t)(b*T_ + t0 + tid) * H_ + h];
    }

    float acc1[4][4], acc2[4][4];
    #pragma unroll
    for (int i = 0; i < 4; i++)
        #pragma unroll
        for (int j = 0; j < 4; j++) { acc1[i][j] = 0.f; acc2[i][j] = 0.f; }

    const int nChunk = t0/64 + 1;
    const int nTiles = nChunk + (2*M_)/64;

    for (int it = 0; it < nTiles; it++) {
        const bool isMem  = (it >= nChunk);
        const int  s0     = isMem ? (T_ + (it - nChunk)*64) : it*64;
        const bool isDiag = (!isMem) && (s0 == t0);

        __syncthreads();
        {
            int r  = tid >> 2;
            int c0 = (tid & 3) * 16;
            const float* src = k + (size_t)(b*S_ + s0 + r) * C_ + h*HD_ + c0;
            #pragma unroll
            for (int u = 0; u < 16; u++)
                KV[(c0 + u)*APAD + r] = src[u];
        }
        __syncthreads();

        float sc[4][4];
        #pragma unroll
        for (int i = 0; i < 4; i++)
            #pragma unroll
            for (int j = 0; j < 4; j++) sc[i][j] = 0.f;
        #pragma unroll 4
        for (int d = 0; d < 64; d++) {
            float aq[4];
            #pragma unroll
            for (int ii = 0; ii < 4; ii++) aq[ii] = Qs[(ty*4+ii)*APAD + d];
            float4 bk = *(const float4*)&KV[d*APAD + (tx<<2)];
            #pragma unroll
            for (int ii = 0; ii < 4; ii++) {
                sc[ii][0] += aq[ii]*bk.x; sc[ii][1] += aq[ii]*bk.y;
                sc[ii][2] += aq[ii]*bk.z; sc[ii][3] += aq[ii]*bk.w;
            }
        }
        #pragma unroll
        for (int ii = 0; ii < 4; ii++) {
            int trow = t0 + ty*4 + ii;
            float4 w;
            float vv0 = sc[ii][0]*scale, vv1 = sc[ii][1]*scale;
            float vv2 = sc[ii][2]*scale, vv3 = sc[ii][3]*scale;
            if (isDiag) {
                int sbase = s0 + (tx<<2);
                if (sbase + 0 > trow) vv0 = -1e30f;
                if (sbase + 1 > trow) vv1 = -1e30f;
                if (sbase + 2 > trow) vv2 = -1e30f;
                if (sbase + 3 > trow) vv3 = -1e30f;
            }
            w.x = vv0; w.y = vv1; w.z = vv2; w.w = vv3;
            *(float4*)&P[(ty*4+ii)*APAD + (tx<<2)] = w;
        }
        __syncthreads();

        {
            int r  = tid >> 2;
            int c0 = (tid & 3) * 16;
            const float* src = v + (size_t)(b*S_ + s0 + r) * C_ + h*HD_ + c0;
            #pragma unroll
            for (int u = 0; u < 4; u++)
                *(float4*)&KV[r*APAD + c0 + u*4] = *(const float4*)(src + u*4);
        }
        if (tid < 64) {
            float mx = -1e30f;
            #pragma unroll 8
            for (int c = 0; c < 64; c++) mx = fmaxf(mx, P[tid*APAD + c]);
            float mold = rowm[tid];
            float mnew = fmaxf(mold, mx);
            rowf[tid] = __expf(mold - mnew);
            rowm[tid] = mnew;
        }
        __syncthreads();

        #pragma unroll
        for (int ii = 0; ii < 4; ii++) {
            int r = ty*4 + ii;
            float mr = rowm[r];
            float fr = rowf[r];
            float* pp = &P[r*APAD + (tx<<2)];
            float4 pv = *(float4*)pp;
            pv.x = __expf(pv.x - mr); pv.y = __expf(pv.y - mr);
            pv.z = __expf(pv.z - mr); pv.w = __expf(pv.w - mr);
            *(float4*)pp = pv;
            #pragma unroll
            for (int jj = 0; jj < 4; jj++) { acc1[ii][jj] *= fr; acc2[ii][jj] *= fr; }
        }
        __syncthreads();

        if (tid < 64) {
            float s = 0.f;
            #pragma unroll 8
            for (int c = 0; c < 64; c++) s += P[tid*APAD + c];
            rowl[tid] = rowl[tid] * rowf[tid] + s;
        }

#define PV_LOOP(ACC)                                                        \
        _Pragma("unroll 4")                                                 \
        for (int j = 0; j < 64; j++) {                                      \
            float4 vv = *(const float4*)&KV[j*APAD + (tx<<2)];              \
            float pq[4];                                                    \
            _Pragma("unroll")                                               \
            for (int ii = 0; ii < 4; ii++) pq[ii] = P[(ty*4+ii)*APAD + j];  \
            _Pragma("unroll")                                               \
            for (int ii = 0; ii < 4; ii++) {                                \
                ACC[ii][0] += pq[ii]*vv.x; ACC[ii][1] += pq[ii]*vv.y;       \
                ACC[ii][2] += pq[ii]*vv.z; ACC[ii][3] += pq[ii]*vv.w;       \
            }                                                               \
        }
        if (!isMem) { PV_LOOP(acc1) } else { PV_LOOP(acc2) }
#undef PV_LOOP
    }
    __syncthreads();

    #pragma unroll
    for (int ii = 0; ii < 4; ii++) {
        int r = ty*4 + ii;
        float inv = 1.f / rowl[r];
        float gg  = gsm[r];
        float4 o;
        o.x = (acc1[ii][0] + gg*acc2[ii][0]) * inv;
        o.y = (acc1[ii][1] + gg*acc2[ii][1]) * inv;
        o.z = (acc1[ii][2] + gg*acc2[ii][2]) * inv;
        o.w = (acc1[ii][3] + gg*acc2[ii][3]) * inv;
        *(float4*)&outp[(size_t)(b*T_ + t0 + r) * C_ + h*HD_ + (tx<<2)] = o;
    }
}

// ---------------- canon conv: z = y + depthwise_causal_conv(y) + bias -----
__global__ __launch_bounds__(256)
void conv_kernel(const float* __restrict__ y, const float* __restrict__ cw,
                 const float* __restrict__ cb, float* __restrict__ z) {
    int idx = blockIdx.x * 256 + threadIdx.x;
    if (idx >= B_*T_*C_) return;
    int c = idx % C_;
    int t = (idx / C_) % T_;
    int b = idx / (C_ * T_);
    float s = y[idx] + cb[c];
    #pragma unroll
    for (int j = 0; j < KC_; j++) {
        int tt = t - (KC_ - 1) + j;
        if (tt >= 0)
            s += y[((size_t)(b*T_ + tt)) * C_ + c] * cw[c*KC_ + j];
    }
    z[idx] = s;
}

// ---------------- orchestration -------------------------------------------
extern "C" void kernel_launch(void* const* d_in, const int* in_sizes, int n_in,
                              void* d_out, int out_size) {
    const float* x   = (const float*)d_in[0];
    const float* fwd = (const float*)d_in[1];
    const float* rev = (const float*)d_in[2];
    const float* Wq  = (const float*)d_in[3];
    const float* Wk  = (const float*)d_in[4];
    const float* Wv  = (const float*)d_in[5];
    const float* Wo  = (const float*)d_in[6];
    const float* gw  = (const float*)d_in[7];
    const float* gb  = (const float*)d_in[8];
    const float* cw  = (const float*)d_in[9];
    const float* cb  = (const float*)d_in[10];
    float* out = (float*)d_out;

    float *xc, *qb, *kb, *vb, *gt, *at, *zb;
    cudaGetSymbolAddress((void**)&xc, g_xcat);
    cudaGetSymbolAddress((void**)&qb, g_q);
    cudaGetSymbolAddress((void**)&kb, g_k);
    cudaGetSymbolAddress((void**)&vb, g_v);
    cudaGetSymbolAddress((void**)&gt, g_gate);
    cudaGetSymbolAddress((void**)&at, g_attn);
    cudaGetSymbolAddress((void**)&zb, g_z);

    cudaFuncSetAttribute(attn_kernel,
                         cudaFuncAttributeMaxDynamicSharedMemorySize, ATT_SMEM);
    cudaFuncSetAttribute(gemm_tf32,
                         cudaFuncAttributeMaxDynamicSharedMemorySize, GEMM_SMEM);

    // 1. pack concat(x, fwd, rev)
    {
        int n4 = B_*S_*(C_/4);
        pack_kernel<<<(n4 + 255)/256, 256>>>((const float4*)x, (const float4*)fwd,
                                             (const float4*)rev, (float4*)xc);
    }
    // 2. projections (NT gemms: out[m,n] = in[m,:] . W[n,:]) on tensor cores
    gemm_tf32<<<dim3(C_/128, (B_*T_)/128), 256, GEMM_SMEM>>>(x,  Wq, qb, B_*T_, C_, C_);
    gemm_tf32<<<dim3(C_/128, (B_*S_)/128), 256, GEMM_SMEM>>>(xc, Wk, kb, B_*S_, C_, C_);
    gemm_tf32<<<dim3(C_/128, (B_*S_)/128), 256, GEMM_SMEM>>>(xc, Wv, vb, B_*S_, C_, C_);
    // 3. gate (needs q)
    gate_kernel<<<B_*T_, 256>>>(qb, gw, gb, gt);
    // 4. attention
    attn_kernel<<<dim3(T_/64, B_*H_), 256, ATT_SMEM>>>(qb, kb, vb, gt, at);
    // 5. canon conv
    conv_kernel<<<(B_*T_*C_ + 255)/256, 256>>>(at, cw, cb, zb);
    // 6. output projection straight into d_out
    gemm_tf32<<<dim3(C_/128, (B_*T_)/128), 256, GEMM_SMEM>>>(zb, Wo, out, B_*T_, C_, C_);
}

// round 3
// speedup vs baseline: 2.3220x; 1.5138x over previous
#include <cuda_runtime.h>
#include <math.h>
#include <stdint.h>

#define B_ 2
#define T_ 2048
#define C_ 1024
#define H_ 16
#define HD_ 64
#define M_ 256
#define S_ (T_ + 2*M_)   /* 2560 */
#define KC_ 4

// ---------------- scratch (static device globals; no runtime alloc) -------
__device__ float g_xcat[B_*S_*C_];
__device__ float g_q  [B_*T_*C_];
__device__ float g_k  [B_*S_*C_];
__device__ float g_v  [B_*S_*C_];
__device__ float g_gate[B_*T_*H_];
__device__ float g_attn[B_*T_*C_];
__device__ float g_z  [B_*T_*C_];

// ---------------- pack ----------------------------------------------------
__global__ void pack_kernel(const float4* __restrict__ x,
                            const float4* __restrict__ fwd,
                            const float4* __restrict__ rev,
                            float4* __restrict__ xc) {
    const int C4 = C_/4;
    int idx = blockIdx.x * 256 + threadIdx.x;
    if (idx >= B_*S_*C4) return;
    int c4 = idx % C4;
    int r  = (idx / C4) % S_;
    int b  = idx / (C4 * S_);
    float4 val;
    if (r < T_)            val = x  [(b*T_ + r)          * C4 + c4];
    else if (r < T_ + M_)  val = fwd[(b*M_ + (r - T_))   * C4 + c4];
    else                   val = rev[(b*M_ + (r - T_-M_))* C4 + c4];
    xc[idx] = val;
}

// ================= TF32 helpers ===========================================
__device__ __forceinline__ uint32_t f2tf32(float f) {
    uint32_t r;
    asm("cvt.rna.tf32.f32 %0, %1;" : "=r"(r) : "f"(f));
    return r;
}
__device__ __forceinline__ void mma_tf32(float* d, const uint32_t* a,
                                         const uint32_t* b) {
    asm volatile(
        "mma.sync.aligned.m16n8k8.row.col.f32.tf32.tf32.f32 "
        "{%0,%1,%2,%3}, {%4,%5,%6,%7}, {%8,%9}, {%0,%1,%2,%3};"
        : "+f"(d[0]), "+f"(d[1]), "+f"(d[2]), "+f"(d[3])
        : "r"(a[0]), "r"(a[1]), "r"(a[2]), "r"(a[3]),
          "r"(b[0]), "r"(b[1]));
}

// ================= TF32 tensor-core GEMM (NT) ==============================
#define GBM 128
#define GBN 128
#define GBK 32
#define GPAD 36
#define GEMM_SMEM (2 * (GBM + GBN) * GPAD * (int)sizeof(uint32_t))

__global__ __launch_bounds__(256)
void gemm_tf32(const float* __restrict__ A, const float* __restrict__ Bm,
               float* __restrict__ Cm, int Mr, int Nr, int Kr) {
    extern __shared__ uint32_t smtf[];
    uint32_t* As = smtf;
    uint32_t* Bs = smtf + 2 * GBM * GPAD;

    const int tid  = threadIdx.x;
    const int lane = tid & 31, warp = tid >> 5;
    const int g = lane >> 2, qc = lane & 3;
    const int wm0 = (warp >> 2) * 64;
    const int wn0 = (warp & 3) * 32;
    const int m0 = blockIdx.y * GBM, n0 = blockIdx.x * GBN;

    const int ldr = tid >> 1;
    const int ldc = (tid & 1) * 16;
    const float* Ag = A  + (size_t)(m0 + ldr) * Kr + ldc;
    const float* Bg = Bm + (size_t)(n0 + ldr) * Kr + ldc;

    float acc[4][4][4] = {};

    float4 ra[4], rb[4];
    #pragma unroll
    for (int u = 0; u < 4; u++) {
        ra[u] = *(const float4*)(Ag + u*4);
        rb[u] = *(const float4*)(Bg + u*4);
    }
    {
        uint32_t* as = As + ldr * GPAD + ldc;
        uint32_t* bs = Bs + ldr * GPAD + ldc;
        #pragma unroll
        for (int u = 0; u < 4; u++) {
            uint4 ua = make_uint4(f2tf32(ra[u].x), f2tf32(ra[u].y),
                                  f2tf32(ra[u].z), f2tf32(ra[u].w));
            uint4 ub = make_uint4(f2tf32(rb[u].x), f2tf32(rb[u].y),
                                  f2tf32(rb[u].z), f2tf32(rb[u].w));
            *(uint4*)(as + u*4) = ua;
            *(uint4*)(bs + u*4) = ub;
        }
    }
    __syncthreads();

    const int nk = Kr / GBK;
    for (int kt = 0; kt < nk; kt++) {
        const int cur = kt & 1;
        if (kt + 1 < nk) {
            const float* Ap = Ag + (size_t)(kt + 1) * GBK;
            const float* Bp = Bg + (size_t)(kt + 1) * GBK;
            #pragma unroll
            for (int u = 0; u < 4; u++) {
                ra[u] = *(const float4*)(Ap + u*4);
                rb[u] = *(const float4*)(Bp + u*4);
            }
        }
        const uint32_t* as = As + cur * GBM * GPAD;
        const uint32_t* bs = Bs + cur * GBN * GPAD;
        #pragma unroll
        for (int kp = 0; kp < 4; kp++) {
            const int k0 = kp * 8;
            uint32_t af[4][4], bf[4][2];
            #pragma unroll
            for (int mt = 0; mt < 4; mt++) {
                int r = wm0 + mt*16 + g;
                af[mt][0] = as[(size_t)r      * GPAD + k0 + qc];
                af[mt][1] = as[(size_t)(r+8)  * GPAD + k0 + qc];
                af[mt][2] = as[(size_t)r      * GPAD + k0 + qc + 4];
                af[mt][3] = as[(size_t)(r+8)  * GPAD + k0 + qc + 4];
            }
            #pragma unroll
            for (int nt = 0; nt < 4; nt++) {
                int r = wn0 + nt*8 + g;
                bf[nt][0] = bs[(size_t)r * GPAD + k0 + qc];
                bf[nt][1] = bs[(size_t)r * GPAD + k0 + qc + 4];
            }
            #pragma unroll
            for (int mt = 0; mt < 4; mt++)
                #pragma unroll
                for (int nt = 0; nt < 4; nt++)
                    mma_tf32(acc[mt][nt], af[mt], bf[nt]);
        }
        if (kt + 1 < nk) {
            __syncthreads();
            uint32_t* asn = As + (cur ^ 1) * GBM * GPAD + ldr * GPAD + ldc;
            uint32_t* bsn = Bs + (cur ^ 1) * GBN * GPAD + ldr * GPAD + ldc;
            #pragma unroll
            for (int u = 0; u < 4; u++) {
                uint4 ua = make_uint4(f2tf32(ra[u].x), f2tf32(ra[u].y),
                                      f2tf32(ra[u].z), f2tf32(ra[u].w));
                uint4 ub = make_uint4(f2tf32(rb[u].x), f2tf32(rb[u].y),
                                      f2tf32(rb[u].z), f2tf32(rb[u].w));
                *(uint4*)(asn + u*4) = ua;
                *(uint4*)(bsn + u*4) = ub;
            }
            __syncthreads();
        }
    }

    #pragma unroll
    for (int mt = 0; mt < 4; mt++) {
        #pragma unroll
        for (int nt = 0; nt < 4; nt++) {
            int row = m0 + wm0 + mt*16 + g;
            int col = n0 + wn0 + nt*8 + qc*2;
            float2 lo = make_float2(acc[mt][nt][0], acc[mt][nt][1]);
            float2 hi = make_float2(acc[mt][nt][2], acc[mt][nt][3]);
            *(float2*)(Cm + (size_t)row     * Nr + col) = lo;
            *(float2*)(Cm + (size_t)(row+8) * Nr + col) = hi;
        }
    }
}

// ---------------- gate -----------------------------------------------------
__global__ __launch_bounds__(256)
void gate_kernel(const float* __restrict__ q, const float* __restrict__ gw,
                 const float* __restrict__ gb, float* __restrict__ gate) {
    __shared__ float qrow[C_];
    const int bt = blockIdx.x;
    for (int c = threadIdx.x; c < C_; c += 256)
        qrow[c] = q[(size_t)bt * C_ + c];
    __syncthreads();
    const int warp = threadIdx.x >> 5, lane = threadIdx.x & 31;
    for (int h = warp; h < H_; h += 8) {
        float s = 0.f;
        for (int c = lane; c < C_; c += 32)
            s += qrow[c] * gw[h * C_ + c];
        #pragma unroll
        for (int o = 16; o; o >>= 1) s += __shfl_xor_sync(0xffffffffu, s, o);
        if (lane == 0)
            gate[(size_t)bt * H_ + h] = 1.f / (1.f + __expf(-(s + gb[h])));
    }
}

// ================= tensor-core flash attention =============================
// CTA: 64 q rows, 4 warps (16 rows/warp). Tile 64 keys. tf32 mma everywhere.
// Smem: QPs[64][SP] (Q tf32 then reused as P), Ks[64][SP] (cols d-permuted),
// Vt[64][SP] (rows d, cols j-permuted). SP=72 -> conflict-free LDS.64 frags.
#define SP 72
#define ATT2_SMEM (3 * 64 * SP * (int)sizeof(uint32_t))   // 55296 B

__device__ __forceinline__ int pp8(int c) {            // c in 0..7
    return ((c & 3) << 1) | (c >> 2);                   // (qc, qc+4)->(2qc,2qc+1)
}

__global__ __launch_bounds__(128, 3)
void attn_tc(const float* __restrict__ q, const float* __restrict__ k,
             const float* __restrict__ v, const float* __restrict__ gate,
             float* __restrict__ outp) {
    extern __shared__ uint32_t s2[];
    uint32_t* QPs = s2;                 // Q (preload) then P
    uint32_t* Ks  = s2 + 64 * SP;
    uint32_t* Vt  = s2 + 2 * 64 * SP;

    const int tid  = threadIdx.x;
    const int lane = tid & 31, warp = tid >> 5;
    const int g = lane >> 2, qc = lane & 3;
    const int wr0 = warp * 16;
    const int b  = blockIdx.y >> 4;
    const int h  = blockIdx.y & 15;
    const int t0 = (gridDim.x - 1 - blockIdx.x) * 64;   // heavy tiles first

    // ---- load Q rows (own warp rows), scale folded, cols d-permuted ----
    {
        int r  = tid >> 1;                 // = wr0 + (lane>>1)
        int c0 = (tid & 1) * 32;
        const float* src = q + (size_t)(b*T_ + t0 + r) * C_ + h*HD_ + c0;
        #pragma unroll
        for (int u = 0; u < 8; u++) {
            float4 vv = *(const float4*)(src + u*4);
            int dbase = c0 + u*4;
            float e[4] = {vv.x, vv.y, vv.z, vv.w};
            #pragma unroll
            for (int t = 0; t < 4; t++) {
                int d = dbase + t;
                QPs[r*SP + (d & ~7) + pp8(d & 7)] = f2tf32(e[t] * 0.125f);
            }
        }
    }
    __syncwarp();
    // ---- preload Q fragments (LDS.64, conflict-free) ----
    uint32_t qf[8][4];
    #pragma unroll
    for (int kk = 0; kk < 8; kk++) {
        uint2 u0 = *(const uint2*)&QPs[(wr0 + g    ) * SP + kk*8 + 2*qc];
        uint2 u1 = *(const uint2*)&QPs[(wr0 + g + 8) * SP + kk*8 + 2*qc];
        qf[kk][0] = u0.x; qf[kk][1] = u1.x; qf[kk][2] = u0.y; qf[kk][3] = u1.y;
    }
    __syncwarp();

    float oc[8][4] = {}, om[8][4] = {};
    float mA = -1e30f, mB = -1e30f, lA = 0.f, lB = 0.f;

    const int nChunk = t0/64 + 1;
    const int nTiles = nChunk + (2*M_)/64;

    for (int it = 0; it < nTiles; it++) {
        const bool isMem  = (it >= nChunk);
        const int  s0     = isMem ? (T_ + (it - nChunk)*64) : it*64;
        const bool isDiag = (!isMem) && (s0 == t0);

        __syncthreads();   // prior mma reads of Ks/Vt complete
        // ---- load K tile: rows j natural, cols d permuted ----
        {
            int r  = tid >> 1;
            int c0 = (tid & 1) * 32;
            const float* srck = k + (size_t)(b*S_ + s0 + r) * C_ + h*HD_ + c0;
            const float* srcv = v + (size_t)(b*S_ + s0 + r) * C_ + h*HD_ + c0;
            int jphys = (r & ~7) + pp8(r & 7);
            #pragma unroll
            for (int u = 0; u < 8; u++) {
                float4 kv = *(const float4*)(srck + u*4);
                float4 vv = *(const float4*)(srcv + u*4);
                int dbase = c0 + u*4;
                float ek[4] = {kv.x, kv.y, kv.z, kv.w};
                float ev[4] = {vv.x, vv.y, vv.z, vv.w};
                #pragma unroll
                for (int t = 0; t < 4; t++) {
                    int d = dbase + t;
                    Ks[r*SP + (d & ~7) + pp8(d & 7)] = f2tf32(ek[t]);
                    Vt[d*SP + jphys] = f2tf32(ev[t]);
                }
            }
        }
        __syncthreads();

        // ---- S = Q K^T (per warp: 16 x 64) ----
        float sf[8][4] = {};
        #pragma unroll
        for (int f = 0; f < 8; f++) {
            #pragma unroll
            for (int kk = 0; kk < 8; kk++) {
                uint2 bu = *(const uint2*)&Ks[(f*8 + g)*SP + kk*8 + 2*qc];
                uint32_t bf[2] = {bu.x, bu.y};
                mma_tf32(sf[f], qf[kk], bf);
            }
        }

        // ---- mask (diag tile) + row max ----
        float tmA = -1e30f, tmB = -1e30f;
        #pragma unroll
        for (int f = 0; f < 8; f++) {
            if (isDiag) {
                int c0 = f*8 + 2*qc, c1 = c0 + 1;
                int rA = wr0 + g, rB = rA + 8;
                if (c0 > rA) sf[f][0] = -1e30f;
                if (c1 > rA) sf[f][1] = -1e30f;
                if (c0 > rB) sf[f][2] = -1e30f;
                if (c1 > rB) sf[f][3] = -1e30f;
            }
            tmA = fmaxf(tmA, fmaxf(sf[f][0], sf[f][1]));
            tmB = fmaxf(tmB, fmaxf(sf[f][2], sf[f][3]));
        }
        tmA = fmaxf(tmA, __shfl_xor_sync(~0u, tmA, 1));
        tmA = fmaxf(tmA, __shfl_xor_sync(~0u, tmA, 2));
        tmB = fmaxf(tmB, __shfl_xor_sync(~0u, tmB, 1));
        tmB = fmaxf(tmB, __shfl_xor_sync(~0u, tmB, 2));

        float mAn = fmaxf(mA, tmA), mBn = fmaxf(mB, tmB);
        float fA = __expf(mA - mAn), fB = __expf(mB - mBn);
        mA = mAn; mB = mBn;

        // ---- P = exp(S - m), store to smem (natural cols), row sums ----
        float sA = 0.f, sB = 0.f;
        #pragma unroll
        for (int f = 0; f < 8; f++) {
            float p0 = __expf(sf[f][0] - mA);
            float p1 = __expf(sf[f][1] - mA);
            float p2 = __expf(sf[f][2] - mB);
            float p3 = __expf(sf[f][3] - mB);
            sA += p0 + p1; sB += p2 + p3;
            uint2 lo = make_uint2(f2tf32(p0), f2tf32(p1));
            uint2 hi = make_uint2(f2tf32(p2), f2tf32(p3));
            *(uint2*)&QPs[(wr0 + g    )*SP + f*8 + 2*qc] = lo;
            *(uint2*)&QPs[(wr0 + g + 8)*SP + f*8 + 2*qc] = hi;
        }
        sA += __shfl_xor_sync(~0u, sA, 1); sA += __shfl_xor_sync(~0u, sA, 2);
        sB += __shfl_xor_sync(~0u, sB, 1); sB += __shfl_xor_sync(~0u, sB, 2);
        lA = lA * fA + sA;
        lB = lB * fB + sB;

        // ---- rescale accumulators ----
        #pragma unroll
        for (int f = 0; f < 8; f++) {
            oc[f][0] *= fA; oc[f][1] *= fA; oc[f][2] *= fB; oc[f][3] *= fB;
            om[f][0] *= fA; om[f][1] *= fA; om[f][2] *= fB; om[f][3] *= fB;
        }
        __syncwarp();

        // ---- load P fragments (A operand for PV) ----
        uint32_t pf[8][4];
        #pragma unroll
        for (int kk = 0; kk < 8; kk++) {
            pf[kk][0] = QPs[(wr0 + g    )*SP + kk*8 + qc];
            pf[kk][1] = QPs[(wr0 + g + 8)*SP + kk*8 + qc];
            pf[kk][2] = QPs[(wr0 + g    )*SP + kk*8 + qc + 4];
            pf[kk][3] = QPs[(wr0 + g + 8)*SP + kk*8 + qc + 4];
        }

        // ---- O += P V  (B = Vt, rows d, cols j permuted) ----
        float (*accp)[4] = isMem ? om : oc;
        #pragma unroll
        for (int f = 0; f < 8; f++) {
            #pragma unroll
            for (int kk = 0; kk < 8; kk++) {
                uint2 bu = *(const uint2*)&Vt[(f*8 + g)*SP + kk*8 + 2*qc];
                uint32_t bf[2] = {bu.x, bu.y};
                mma_tf32(accp[f], pf[kk], bf);
            }
        }
    }

    // ---- epilogue: Y = (oc + gate * om) / l ----
    int rA = t0 + wr0 + g, rB = rA + 8;
    float gA = gate[(size_t)(b*T_ + rA) * H_ + h];
    float gB = gate[(size_t)(b*T_ + rB) * H_ + h];
    float invA = 1.f / lA, invB = 1.f / lB;
    #pragma unroll
    for (int f = 0; f < 8; f++) {
        int col = h*HD_ + f*8 + 2*qc;
        float2 o0 = make_float2((oc[f][0] + gA*om[f][0]) * invA,
                                (oc[f][1] + gA*om[f][1]) * invA);
        float2 o1 = make_float2((oc[f][2] + gB*om[f][2]) * invB,
                                (oc[f][3] + gB*om[f][3]) * invB);
        *(float2*)&outp[(size_t)(b*T_ + rA) * C_ + col] = o0;
        *(float2*)&outp[(size_t)(b*T_ + rB) * C_ + col] = o1;
    }
}

// ---------------- canon conv -----------------------------------------------
__global__ __launch_bounds__(256)
void conv_kernel(const float* __restrict__ y, const float* __restrict__ cw,
                 const float* __restrict__ cb, float* __restrict__ z) {
    int idx = blockIdx.x * 256 + threadIdx.x;
    if (idx >= B_*T_*C_) return;
    int c = idx % C_;
    int t = (idx / C_) % T_;
    int b = idx / (C_ * T_);
    float s = y[idx] + cb[c];
    #pragma unroll
    for (int j = 0; j < KC_; j++) {
        int tt = t - (KC_ - 1) + j;
        if (tt >= 0)
            s += y[((size_t)(b*T_ + tt)) * C_ + c] * cw[c*KC_ + j];
    }
    z[idx] = s;
}

// ---------------- orchestration -------------------------------------------
extern "C" void kernel_launch(void* const* d_in, const int* in_sizes, int n_in,
                              void* d_out, int out_size) {
    const float* x   = (const float*)d_in[0];
    const float* fwd = (const float*)d_in[1];
    const float* rev = (const float*)d_in[2];
    const float* Wq  = (const float*)d_in[3];
    const float* Wk  = (const float*)d_in[4];
    const float* Wv  = (const float*)d_in[5];
    const float* Wo  = (const float*)d_in[6];
    const float* gw  = (const float*)d_in[7];
    const float* gb  = (const float*)d_in[8];
    const float* cw  = (const float*)d_in[9];
    const float* cb  = (const float*)d_in[10];
    float* out = (float*)d_out;

    float *xc, *qb, *kb, *vb, *gt, *at, *zb;
    cudaGetSymbolAddress((void**)&xc, g_xcat);
    cudaGetSymbolAddress((void**)&qb, g_q);
    cudaGetSymbolAddress((void**)&kb, g_k);
    cudaGetSymbolAddress((void**)&vb, g_v);
    cudaGetSymbolAddress((void**)&gt, g_gate);
    cudaGetSymbolAddress((void**)&at, g_attn);
    cudaGetSymbolAddress((void**)&zb, g_z);

    cudaFuncSetAttribute(gemm_tf32,
                         cudaFuncAttributeMaxDynamicSharedMemorySize, GEMM_SMEM);
    cudaFuncSetAttribute(attn_tc,
                         cudaFuncAttributeMaxDynamicSharedMemorySize, ATT2_SMEM);

    {
        int n4 = B_*S_*(C_/4);
        pack_kernel<<<(n4 + 255)/256, 256>>>((const float4*)x, (const float4*)fwd,
                                             (const float4*)rev, (float4*)xc);
    }
    gemm_tf32<<<dim3(C_/128, (B_*T_)/128), 256, GEMM_SMEM>>>(x,  Wq, qb, B_*T_, C_, C_);
    gemm_tf32<<<dim3(C_/128, (B_*S_)/128), 256, GEMM_SMEM>>>(xc, Wk, kb, B_*S_, C_, C_);
    gemm_tf32<<<dim3(C_/128, (B_*S_)/128), 256, GEMM_SMEM>>>(xc, Wv, vb, B_*S_, C_, C_);
    gate_kernel<<<B_*T_, 256>>>(qb, gw, gb, gt);
    attn_tc<<<dim3(T_/64, B_*H_), 128, ATT2_SMEM>>>(qb, kb, vb, gt, at);
    conv_kernel<<<(B_*T_*C_ + 255)/256, 256>>>(at, cw, cb, zb);
    gemm_tf32<<<dim3(C_/128, (B_*T_)/128), 256, GEMM_SMEM>>>(zb, Wo, out, B_*T_, C_, C_);
}

// round 4
// speedup vs baseline: 2.6595x; 1.1453x over previous
#include <cuda_runtime.h>
#include <math.h>
#include <stdint.h>

#define B_ 2
#define T_ 2048
#define C_ 1024
#define H_ 16
#define HD_ 64
#define M_ 256
#define S_ (T_ + 2*M_)   /* 2560 */
#define KC_ 4

// ---------------- scratch (static device globals; no runtime alloc) -------
__device__ uint32_t g_xcat[B_*S_*C_];   // concat(x,fwd,rev) as tf32 bits
__device__ uint32_t g_xtf [B_*T_*C_];   // x as tf32 bits
__device__ uint32_t g_wtf [4*C_*C_];    // Wq|Wk|Wv|Wo as tf32 bits
__device__ float    g_q   [B_*T_*C_];
__device__ float    g_k   [B_*S_*C_];
__device__ float    g_v   [B_*S_*C_];
__device__ float    g_gate[B_*T_*H_];
__device__ float    g_attn[B_*T_*C_];
__device__ uint32_t g_ztf [B_*T_*C_];   // conv output as tf32 bits

// ================= TF32 helpers ===========================================
__device__ __forceinline__ uint32_t f2tf32(float f) {
    uint32_t r;
    asm("cvt.rna.tf32.f32 %0, %1;" : "=r"(r) : "f"(f));
    return r;
}
__device__ __forceinline__ void mma_tf32(float* d, const uint32_t* a,
                                         const uint32_t* b) {
    asm volatile(
        "mma.sync.aligned.m16n8k8.row.col.f32.tf32.tf32.f32 "
        "{%0,%1,%2,%3}, {%4,%5,%6,%7}, {%8,%9}, {%0,%1,%2,%3};"
        : "+f"(d[0]), "+f"(d[1]), "+f"(d[2]), "+f"(d[3])
        : "r"(a[0]), "r"(a[1]), "r"(a[2]), "r"(a[3]),
          "r"(b[0]), "r"(b[1]));
}
__device__ __forceinline__ void ldsm_x4(uint32_t* r, uint32_t addr) {
    asm volatile("ldmatrix.sync.aligned.m8n8.x4.shared.b16 {%0,%1,%2,%3}, [%4];"
        : "=r"(r[0]), "=r"(r[1]), "=r"(r[2]), "=r"(r[3]) : "r"(addr));
}
__device__ __forceinline__ void cp16(uint32_t dst, const void* src) {
    asm volatile("cp.async.cg.shared.global [%0], [%1], 16;" :: "r"(dst), "l"(src));
}

// ---------------- pack: xcat = concat(x, fwd, rev) -> tf32 bits ----------
__global__ void pack_kernel(const float4* __restrict__ x,
                            const float4* __restrict__ fwd,
                            const float4* __restrict__ rev,
                            uint4* __restrict__ xc) {
    const int C4 = C_/4;
    int idx = blockIdx.x * 256 + threadIdx.x;
    if (idx >= B_*S_*C4) return;
    int c4 = idx % C4;
    int r  = (idx / C4) % S_;
    int b  = idx / (C4 * S_);
    float4 val;
    if (r < T_)            val = x  [(b*T_ + r)          * C4 + c4];
    else if (r < T_ + M_)  val = fwd[(b*M_ + (r - T_))   * C4 + c4];
    else                   val = rev[(b*M_ + (r - T_-M_))* C4 + c4];
    xc[idx] = make_uint4(f2tf32(val.x), f2tf32(val.y), f2tf32(val.z), f2tf32(val.w));
}

// ---------------- cvt kernels ---------------------------------------------
__global__ void wcvt_kernel(const float4* __restrict__ w0, const float4* __restrict__ w1,
                            const float4* __restrict__ w2, const float4* __restrict__ w3,
                            uint4* __restrict__ dst) {
    const int n4 = C_*C_/4;
    int idx = blockIdx.x * 256 + threadIdx.x;
    if (idx >= 4*n4) return;
    int m = idx / n4, r = idx % n4;
    const float4* s = (m == 0) ? w0 : (m == 1) ? w1 : (m == 2) ? w2 : w3;
    float4 v = s[r];
    dst[idx] = make_uint4(f2tf32(v.x), f2tf32(v.y), f2tf32(v.z), f2tf32(v.w));
}
__global__ void xcvt_kernel(const float4* __restrict__ src, uint4* __restrict__ dst, int n4) {
    int idx = blockIdx.x * 256 + threadIdx.x;
    if (idx >= n4) return;
    float4 v = src[idx];
    dst[idx] = make_uint4(f2tf32(v.x), f2tf32(v.y), f2tf32(v.z), f2tf32(v.w));
}

// ================= TF32 GEMM v2: cp.async 3-stage + ldmatrix ==============
// C[m,n] = sum_k A[m,k]*B[n,k], A/B pre-converted tf32 bits.
// BM=BN=128, BK=32, 256 threads (8 warps 2x4, 64x32 each), PAD=36.
#define GBM 128
#define GBN 128
#define GBK 32
#define GPAD 36
#define GSTG (GBM * GPAD)                    // words per operand per stage
#define GSTRIDE (2 * GSTG)                   // words per stage (A then B)
#define GEMM2_SMEM (3 * GSTRIDE * (int)sizeof(uint32_t))   // 110592 B

__global__ __launch_bounds__(256)
void gemm_tc(const uint32_t* __restrict__ A, const uint32_t* __restrict__ Bm,
             float* __restrict__ Cm, int Mr, int Nr, int Kr) {
    extern __shared__ uint32_t smg[];
    const uint32_t sbase = (uint32_t)__cvta_generic_to_shared(smg);

    const int tid  = threadIdx.x;
    const int lane = tid & 31, warp = tid >> 5;
    const int g = lane >> 2, qc = lane & 3;
    const int wm0 = (warp >> 2) * 64;
    const int wn0 = (warp & 3) * 32;
    const int m0 = blockIdx.y * GBM, n0 = blockIdx.x * GBN;
    const int nk = Kr / GBK;

    // ldmatrix per-lane offsets (words)
    const int a_off = ((lane & 7) + ((lane >> 3) & 1) * 8) * GPAD + (lane >> 4) * 4;
    const int b_off = (((lane >> 4) & 1) * 8 + (lane & 7)) * GPAD + ((lane >> 3) & 1) * 4;

    // cp.async per-thread tile coords: 4 chunks of 16B per operand
    // u = tid + j*256 ; row = u>>3 ; c4 = (u&7)*4
    float acc[4][4][4] = {};

    // ---- prefetch helper (inlined twice + loop) ----
    #define PREFETCH(KT)                                                       \
    do {                                                                       \
        int kt_ = (KT);                                                        \
        if (kt_ < nk) {                                                        \
            int slot_ = kt_ % 3;                                               \
            uint32_t da = sbase + (slot_ * GSTRIDE) * 4;                       \
            uint32_t db = da + GSTG * 4;                                       \
            const uint32_t* Ag_ = A  + (size_t)m0 * Kr + kt_ * GBK;            \
            const uint32_t* Bg_ = Bm + (size_t)n0 * Kr + kt_ * GBK;            \
            _Pragma("unroll")                                                  \
            for (int j = 0; j < 4; j++) {                                      \
                int u = tid + j * 256;                                         \
                int row = u >> 3, c4 = (u & 7) * 4;                            \
                cp16(da + (row * GPAD + c4) * 4, Ag_ + (size_t)row * Kr + c4); \
                cp16(db + (row * GPAD + c4) * 4, Bg_ + (size_t)row * Kr + c4); \
            }                                                                  \
        }                                                                      \
        asm volatile("cp.async.commit_group;");                                \
    } while (0)

    PREFETCH(0);
    PREFETCH(1);

    for (int kt = 0; kt < nk; kt++) {
        asm volatile("cp.async.wait_group 1;");
        __syncthreads();
        PREFETCH(kt + 2);

        const int slot = kt % 3;
        const uint32_t aAddr = sbase + (slot * GSTRIDE) * 4 + (wm0 * GPAD + a_off) * 4;
        const uint32_t bAddr = sbase + (slot * GSTRIDE + GSTG) * 4 + (wn0 * GPAD + b_off) * 4;

        #pragma unroll
        for (int kp = 0; kp < 4; kp++) {
            uint32_t bf[4][2];
            {
                uint32_t r[4];
                ldsm_x4(r, bAddr + kp * 32);
                bf[0][0] = r[0]; bf[0][1] = r[1]; bf[1][0] = r[2]; bf[1][1] = r[3];
            }
            {
                uint32_t r[4];
                ldsm_x4(r, bAddr + 16 * GPAD * 4 + kp * 32);
                bf[2][0] = r[0]; bf[2][1] = r[1]; bf[3][0] = r[2]; bf[3][1] = r[3];
            }
            uint32_t af[4][4];
            #pragma unroll
            for (int mt = 0; mt < 4; mt++)
                ldsm_x4(af[mt], aAddr + mt * 16 * GPAD * 4 + kp * 32);
            #pragma unroll
            for (int mt = 0; mt < 4; mt++)
                #pragma unroll
                for (int nt = 0; nt < 4; nt++)
                    mma_tf32(acc[mt][nt], af[mt], bf[nt]);
        }
    }
    #undef PREFETCH

    #pragma unroll
    for (int mt = 0; mt < 4; mt++) {
        #pragma unroll
        for (int nt = 0; nt < 4; nt++) {
            int row = m0 + wm0 + mt*16 + g;
            int col = n0 + wn0 + nt*8 + qc*2;
            float2 lo = make_float2(acc[mt][nt][0], acc[mt][nt][1]);
            float2 hi = make_float2(acc[mt][nt][2], acc[mt][nt][3]);
            *(float2*)(Cm + (size_t)row     * Nr + col) = lo;
            *(float2*)(Cm + (size_t)(row+8) * Nr + col) = hi;
        }
    }
}

// ---------------- gate -----------------------------------------------------
__global__ __launch_bounds__(256)
void gate_kernel(const float* __restrict__ q, const float* __restrict__ gw,
                 const float* __restrict__ gb, float* __restrict__ gate) {
    __shared__ float qrow[C_];
    const int bt = blockIdx.x;
    for (int c = threadIdx.x; c < C_; c += 256)
        qrow[c] = q[(size_t)bt * C_ + c];
    __syncthreads();
    const int warp = threadIdx.x >> 5, lane = threadIdx.x & 31;
    for (int h = warp; h < H_; h += 8) {
        float s = 0.f;
        for (int c = lane; c < C_; c += 32)
            s += qrow[c] * gw[h * C_ + c];
        #pragma unroll
        for (int o = 16; o; o >>= 1) s += __shfl_xor_sync(0xffffffffu, s, o);
        if (lane == 0)
            gate[(size_t)bt * H_ + h] = 1.f / (1.f + __expf(-(s + gb[h])));
    }
}

// ================= tensor-core flash attention (unchanged) =================
#define SP 72
#define ATT2_SMEM (3 * 64 * SP * (int)sizeof(uint32_t))

__device__ __forceinline__ int pp8(int c) {
    return ((c & 3) << 1) | (c >> 2);
}

__global__ __launch_bounds__(128, 3)
void attn_tc(const float* __restrict__ q, const float* __restrict__ k,
             const float* __restrict__ v, const float* __restrict__ gate,
             float* __restrict__ outp) {
    extern __shared__ uint32_t s2[];
    uint32_t* QPs = s2;
    uint32_t* Ks  = s2 + 64 * SP;
    uint32_t* Vt  = s2 + 2 * 64 * SP;

    const int tid  = threadIdx.x;
    const int lane = tid & 31, warp = tid >> 5;
    const int g = lane >> 2, qc = lane & 3;
    const int wr0 = warp * 16;
    const int b  = blockIdx.y >> 4;
    const int h  = blockIdx.y & 15;
    const int t0 = (gridDim.x - 1 - blockIdx.x) * 64;

    {
        int r  = tid >> 1;
        int c0 = (tid & 1) * 32;
        const float* src = q + (size_t)(b*T_ + t0 + r) * C_ + h*HD_ + c0;
        #pragma unroll
        for (int u = 0; u < 8; u++) {
            float4 vv = *(const float4*)(src + u*4);
            int dbase = c0 + u*4;
            float e[4] = {vv.x, vv.y, vv.z, vv.w};
            #pragma unroll
            for (int t = 0; t < 4; t++) {
                int d = dbase + t;
                QPs[r*SP + (d & ~7) + pp8(d & 7)] = f2tf32(e[t] * 0.125f);
            }
        }
    }
    __syncwarp();
    uint32_t qf[8][4];
    #pragma unroll
    for (int kk = 0; kk < 8; kk++) {
        uint2 u0 = *(const uint2*)&QPs[(wr0 + g    ) * SP + kk*8 + 2*qc];
        uint2 u1 = *(const uint2*)&QPs[(wr0 + g + 8) * SP + kk*8 + 2*qc];
        qf[kk][0] = u0.x; qf[kk][1] = u1.x; qf[kk][2] = u0.y; qf[kk][3] = u1.y;
    }
    __syncwarp();

    float oc[8][4] = {}, om[8][4] = {};
    float mA = -1e30f, mB = -1e30f, lA = 0.f, lB = 0.f;

    const int nChunk = t0/64 + 1;
    const int nTiles = nChunk + (2*M_)/64;

    for (int it = 0; it < nTiles; it++) {
        const bool isMem  = (it >= nChunk);
        const int  s0     = isMem ? (T_ + (it - nChunk)*64) : it*64;
        const bool isDiag = (!isMem) && (s0 == t0);

        __syncthreads();
        {
            int r  = tid >> 1;
            int c0 = (tid & 1) * 32;
            const float* srck = k + (size_t)(b*S_ + s0 + r) * C_ + h*HD_ + c0;
            const float* srcv = v + (size_t)(b*S_ + s0 + r) * C_ + h*HD_ + c0;
            int jphys = (r & ~7) + pp8(r & 7);
            #pragma unroll
            for (int u = 0; u < 8; u++) {
                float4 kv = *(const float4*)(srck + u*4);
                float4 vv = *(const float4*)(srcv + u*4);
                int dbase = c0 + u*4;
                float ek[4] = {kv.x, kv.y, kv.z, kv.w};
                float ev[4] = {vv.x, vv.y, vv.z, vv.w};
                #pragma unroll
                for (int t = 0; t < 4; t++) {
                    int d = dbase + t;
                    Ks[r*SP + (d & ~7) + pp8(d & 7)] = f2tf32(ek[t]);
                    Vt[d*SP + jphys] = f2tf32(ev[t]);
                }
            }
        }
        __syncthreads();

        float sf[8][4] = {};
        #pragma unroll
        for (int f = 0; f < 8; f++) {
            #pragma unroll
            for (int kk = 0; kk < 8; kk++) {
                uint2 bu = *(const uint2*)&Ks[(f*8 + g)*SP + kk*8 + 2*qc];
                uint32_t bf[2] = {bu.x, bu.y};
                mma_tf32(sf[f], qf[kk], bf);
            }
        }

        float tmA = -1e30f, tmB = -1e30f;
        #pragma unroll
        for (int f = 0; f < 8; f++) {
            if (isDiag) {
                int c0 = f*8 + 2*qc, c1 = c0 + 1;
                int rA = wr0 + g, rB = rA + 8;
                if (c0 > rA) sf[f][0] = -1e30f;
                if (c1 > rA) sf[f][1] = -1e30f;
                if (c0 > rB) sf[f][2] = -1e30f;
                if (c1 > rB) sf[f][3] = -1e30f;
            }
            tmA = fmaxf(tmA, fmaxf(sf[f][0], sf[f][1]));
            tmB = fmaxf(tmB, fmaxf(sf[f][2], sf[f][3]));
        }
        tmA = fmaxf(tmA, __shfl_xor_sync(~0u, tmA, 1));
        tmA = fmaxf(tmA, __shfl_xor_sync(~0u, tmA, 2));
        tmB = fmaxf(tmB, __shfl_xor_sync(~0u, tmB, 1));
        tmB = fmaxf(tmB, __shfl_xor_sync(~0u, tmB, 2));

        float mAn = fmaxf(mA, tmA), mBn = fmaxf(mB, tmB);
        float fA = __expf(mA - mAn), fB = __expf(mB - mBn);
        mA = mAn; mB = mBn;

        float sA = 0.f, sB = 0.f;
        #pragma unroll
        for (int f = 0; f < 8; f++) {
            float p0 = __expf(sf[f][0] - mA);
            float p1 = __expf(sf[f][1] - mA);
            float p2 = __expf(sf[f][2] - mB);
            float p3 = __expf(sf[f][3] - mB);
            sA += p0 + p1; sB += p2 + p3;
            uint2 lo = make_uint2(f2tf32(p0), f2tf32(p1));
            uint2 hi = make_uint2(f2tf32(p2), f2tf32(p3));
            *(uint2*)&QPs[(wr0 + g    )*SP + f*8 + 2*qc] = lo;
            *(uint2*)&QPs[(wr0 + g + 8)*SP + f*8 + 2*qc] = hi;
        }
        sA += __shfl_xor_sync(~0u, sA, 1); sA += __shfl_xor_sync(~0u, sA, 2);
        sB += __shfl_xor_sync(~0u, sB, 1); sB += __shfl_xor_sync(~0u, sB, 2);
        lA = lA * fA + sA;
        lB = lB * fB + sB;

        #pragma unroll
        for (int f = 0; f < 8; f++) {
            oc[f][0] *= fA; oc[f][1] *= fA; oc[f][2] *= fB; oc[f][3] *= fB;
            om[f][0] *= fA; om[f][1] *= fA; om[f][2] *= fB; om[f][3] *= fB;
        }
        __syncwarp();

        uint32_t pf[8][4];
        #pragma unroll
        for (int kk = 0; kk < 8; kk++) {
            pf[kk][0] = QPs[(wr0 + g    )*SP + kk*8 + qc];
            pf[kk][1] = QPs[(wr0 + g + 8)*SP + kk*8 + qc];
            pf[kk][2] = QPs[(wr0 + g    )*SP + kk*8 + qc + 4];
            pf[kk][3] = QPs[(wr0 + g + 8)*SP + kk*8 + qc + 4];
        }

        float (*accp)[4] = isMem ? om : oc;
        #pragma unroll
        for (int f = 0; f < 8; f++) {
            #pragma unroll
            for (int kk = 0; kk < 8; kk++) {
                uint2 bu = *(const uint2*)&Vt[(f*8 + g)*SP + kk*8 + 2*qc];
                uint32_t bf[2] = {bu.x, bu.y};
                mma_tf32(accp[f], pf[kk], bf);
            }
        }
    }

    int rA = t0 + wr0 + g, rB = rA + 8;
    float gA = gate[(size_t)(b*T_ + rA) * H_ + h];
    float gB = gate[(size_t)(b*T_ + rB) * H_ + h];
    float invA = 1.f / lA, invB = 1.f / lB;
    #pragma unroll
    for (int f = 0; f < 8; f++) {
        int col = h*HD_ + f*8 + 2*qc;
        float2 o0 = make_float2((oc[f][0] + gA*om[f][0]) * invA,
                                (oc[f][1] + gA*om[f][1]) * invA);
        float2 o1 = make_float2((oc[f][2] + gB*om[f][2]) * invB,
                                (oc[f][3] + gB*om[f][3]) * invB);
        *(float2*)&outp[(size_t)(b*T_ + rA) * C_ + col] = o0;
        *(float2*)&outp[(size_t)(b*T_ + rB) * C_ + col] = o1;
    }
}

// ---------------- canon conv -> tf32 bits ----------------------------------
__global__ __launch_bounds__(256)
void conv_kernel(const float* __restrict__ y, const float* __restrict__ cw,
                 const float* __restrict__ cb, uint32_t* __restrict__ z) {
    int idx = blockIdx.x * 256 + threadIdx.x;
    if (idx >= B_*T_*C_) return;
    int c = idx % C_;
    int t = (idx / C_) % T_;
    int b = idx / (C_ * T_);
    float s = y[idx] + cb[c];
    #pragma unroll
    for (int j = 0; j < KC_; j++) {
        int tt = t - (KC_ - 1) + j;
        if (tt >= 0)
            s += y[((size_t)(b*T_ + tt)) * C_ + c] * cw[c*KC_ + j];
    }
    z[idx] = f2tf32(s);
}

// ---------------- orchestration -------------------------------------------
extern "C" void kernel_launch(void* const* d_in, const int* in_sizes, int n_in,
                              void* d_out, int out_size) {
    const float* x   = (const float*)d_in[0];
    const float* fwd = (const float*)d_in[1];
    const float* rev = (const float*)d_in[2];
    const float* Wq  = (const float*)d_in[3];
    const float* Wk  = (const float*)d_in[4];
    const float* Wv  = (const float*)d_in[5];
    const float* Wo  = (const float*)d_in[6];
    const float* gw  = (const float*)d_in[7];
    const float* gb  = (const float*)d_in[8];
    const float* cw  = (const float*)d_in[9];
    const float* cb  = (const float*)d_in[10];
    float* out = (float*)d_out;

    uint32_t *xc, *xtf, *wtf, *ztf;
    float *qb, *kb, *vb, *gt, *at;
    cudaGetSymbolAddress((void**)&xc,  g_xcat);
    cudaGetSymbolAddress((void**)&xtf, g_xtf);
    cudaGetSymbolAddress((void**)&wtf, g_wtf);
    cudaGetSymbolAddress((void**)&ztf, g_ztf);
    cudaGetSymbolAddress((void**)&qb,  g_q);
    cudaGetSymbolAddress((void**)&kb,  g_k);
    cudaGetSymbolAddress((void**)&vb,  g_v);
    cudaGetSymbolAddress((void**)&gt,  g_gate);
    cudaGetSymbolAddress((void**)&at,  g_attn);

    cudaFuncSetAttribute(gemm_tc,
                         cudaFuncAttributeMaxDynamicSharedMemorySize, GEMM2_SMEM);
    cudaFuncSetAttribute(attn_tc,
                         cudaFuncAttributeMaxDynamicSharedMemorySize, ATT2_SMEM);

    // 1. pre-convert inputs
    {
        int n4 = B_*S_*(C_/4);
        pack_kernel<<<(n4 + 255)/256, 256>>>((const float4*)x, (const float4*)fwd,
                                             (const float4*)rev, (uint4*)xc);
    }
    wcvt_kernel<<<(4*C_*C_/4 + 255)/256, 256>>>((const float4*)Wq, (const float4*)Wk,
                                                (const float4*)Wv, (const float4*)Wo,
                                                (uint4*)wtf);
    xcvt_kernel<<<(B_*T_*C_/4 + 255)/256, 256>>>((const float4*)x, (uint4*)xtf,
                                                 B_*T_*C_/4);

    // 2. projections on tensor cores
    gemm_tc<<<dim3(C_/128, (B_*T_)/128), 256, GEMM2_SMEM>>>(xtf, wtf,          qb, B_*T_, C_, C_);
    gemm_tc<<<dim3(C_/128, (B_*S_)/128), 256, GEMM2_SMEM>>>(xc,  wtf + C_*C_,  kb, B_*S_, C_, C_);
    gemm_tc<<<dim3(C_/128, (B_*S_)/128), 256, GEMM2_SMEM>>>(xc,  wtf + 2*C_*C_, vb, B_*S_, C_, C_);
    // 3. gate
    gate_kernel<<<B_*T_, 256>>>(qb, gw, gb, gt);
    // 4. attention
    attn_tc<<<dim3(T_/64, B_*H_), 128, ATT2_SMEM>>>(qb, kb, vb, gt, at);
    // 5. canon conv (writes tf32)
    conv_kernel<<<(B_*T_*C_ + 255)/256, 256>>>(at, cw, cb, ztf);
    // 6. output projection into d_out
    gemm_tc<<<dim3(C_/128, (B_*T_)/128), 256, GEMM2_SMEM>>>(ztf, wtf + 3*C_*C_, out, B_*T_, C_, C_);
}

// round 5
// speedup vs baseline: 3.8623x; 1.4523x over previous
#include <cuda_runtime.h>
#include <math.h>
#include <stdint.h>

#define B_ 2
#define T_ 2048
#define C_ 1024
#define H_ 16
#define HD_ 64
#define M_ 256
#define S_ (T_ + 2*M_)   /* 2560 */
#define KC_ 4

// ---------------- scratch (static device globals; no runtime alloc) -------
__device__ uint32_t g_xcat[B_*S_*C_];   // concat(x,fwd,rev) as tf32 bits
__device__ uint32_t g_xtf [B_*T_*C_];   // x as tf32 bits
__device__ uint32_t g_wtf [4*C_*C_];    // Wq|Wk|Wv|Wo as tf32 bits
__device__ float    g_q   [B_*T_*C_];   // tf32-rounded
__device__ float    g_k   [B_*S_*C_];   // tf32-rounded
__device__ float    g_v   [B_*S_*C_];   // tf32-rounded
__device__ float    g_vt  [B_*C_*S_];   // V transposed per (b,c): [b][c][s]
__device__ float    g_gate[B_*T_*H_];
__device__ float    g_attn[B_*T_*C_];
__device__ uint32_t g_ztf [B_*T_*C_];   // conv output as tf32 bits

// ================= TF32 helpers ===========================================
__device__ __forceinline__ uint32_t f2tf32(float f) {
    uint32_t r;
    asm("cvt.rna.tf32.f32 %0, %1;" : "=r"(r) : "f"(f));
    return r;
}
__device__ __forceinline__ void mma_tf32(float* d, const uint32_t* a,
                                         const uint32_t* b) {
    asm volatile(
        "mma.sync.aligned.m16n8k8.row.col.f32.tf32.tf32.f32 "
        "{%0,%1,%2,%3}, {%4,%5,%6,%7}, {%8,%9}, {%0,%1,%2,%3};"
        : "+f"(d[0]), "+f"(d[1]), "+f"(d[2]), "+f"(d[3])
        : "r"(a[0]), "r"(a[1]), "r"(a[2]), "r"(a[3]),
          "r"(b[0]), "r"(b[1]));
}
__device__ __forceinline__ void ldsm_x4(uint32_t* r, uint32_t addr) {
    asm volatile("ldmatrix.sync.aligned.m8n8.x4.shared.b16 {%0,%1,%2,%3}, [%4];"
        : "=r"(r[0]), "=r"(r[1]), "=r"(r[2]), "=r"(r[3]) : "r"(addr));
}
__device__ __forceinline__ void cp16(uint32_t dst, const void* src) {
    asm volatile("cp.async.cg.shared.global [%0], [%1], 16;" :: "r"(dst), "l"(src));
}

// ---------------- pack: xcat = concat(x, fwd, rev) -> tf32 bits ----------
__global__ void pack_kernel(const float4* __restrict__ x,
                            const float4* __restrict__ fwd,
                            const float4* __restrict__ rev,
                            uint4* __restrict__ xc) {
    const int C4 = C_/4;
    int idx = blockIdx.x * 256 + threadIdx.x;
    if (idx >= B_*S_*C4) return;
    int c4 = idx % C4;
    int r  = (idx / C4) % S_;
    int b  = idx / (C4 * S_);
    float4 val;
    if (r < T_)            val = x  [(b*T_ + r)          * C4 + c4];
    else if (r < T_ + M_)  val = fwd[(b*M_ + (r - T_))   * C4 + c4];
    else                   val = rev[(b*M_ + (r - T_-M_))* C4 + c4];
    xc[idx] = make_uint4(f2tf32(val.x), f2tf32(val.y), f2tf32(val.z), f2tf32(val.w));
}

// ---------------- cvt kernels ---------------------------------------------
__global__ void wcvt_kernel(const float4* __restrict__ w0, const float4* __restrict__ w1,
                            const float4* __restrict__ w2, const float4* __restrict__ w3,
                            uint4* __restrict__ dst) {
    const int n4 = C_*C_/4;
    int idx = blockIdx.x * 256 + threadIdx.x;
    if (idx >= 4*n4) return;
    int m = idx / n4, r = idx % n4;
    const float4* s = (m == 0) ? w0 : (m == 1) ? w1 : (m == 2) ? w2 : w3;
    float4 v = s[r];
    dst[idx] = make_uint4(f2tf32(v.x), f2tf32(v.y), f2tf32(v.z), f2tf32(v.w));
}
__global__ void xcvt_kernel(const float4* __restrict__ src, uint4* __restrict__ dst, int n4) {
    int idx = blockIdx.x * 256 + threadIdx.x;
    if (idx >= n4) return;
    float4 v = src[idx];
    dst[idx] = make_uint4(f2tf32(v.x), f2tf32(v.y), f2tf32(v.z), f2tf32(v.w));
}

// ---------------- V transpose: vT[b][c][s] = v[b][s][c] --------------------
__global__ __launch_bounds__(256)
void vtrans_kernel(const float* __restrict__ v, float* __restrict__ vT) {
    __shared__ float tile[32][33];
    const int tx = threadIdx.x & 31, ty = threadIdx.x >> 5;  // 32 x 8
    const int s0 = blockIdx.x * 32, c0 = blockIdx.y * 32, b = blockIdx.z;
    #pragma unroll
    for (int i = 0; i < 4; i++)
        tile[ty + i*8][tx] = v[((size_t)(b*S_ + s0 + ty + i*8)) * C_ + c0 + tx];
    __syncthreads();
    #pragma unroll
    for (int i = 0; i < 4; i++)
        vT[((size_t)(b*C_ + c0 + ty + i*8)) * S_ + s0 + tx] = tile[tx][ty + i*8];
}

// ================= TF32 GEMM: cp.async 3-stage + ldmatrix ==================
#define GBM 128
#define GBN 128
#define GBK 32
#define GPAD 36
#define GSTG (GBM * GPAD)
#define GSTRIDE (2 * GSTG)
#define GEMM2_SMEM (3 * GSTRIDE * (int)sizeof(uint32_t))

__global__ __launch_bounds__(256)
void gemm_tc(const uint32_t* __restrict__ A, const uint32_t* __restrict__ Bm,
             float* __restrict__ Cm, int Mr, int Nr, int Kr, int rnd) {
    extern __shared__ uint32_t smg[];
    const uint32_t sbase = (uint32_t)__cvta_generic_to_shared(smg);

    const int tid  = threadIdx.x;
    const int lane = tid & 31, warp = tid >> 5;
    const int g = lane >> 2, qc = lane & 3;
    const int wm0 = (warp >> 2) * 64;
    const int wn0 = (warp & 3) * 32;
    const int m0 = blockIdx.y * GBM, n0 = blockIdx.x * GBN;
    const int nk = Kr / GBK;

    const int a_off = ((lane & 7) + ((lane >> 3) & 1) * 8) * GPAD + (lane >> 4) * 4;
    const int b_off = (((lane >> 4) & 1) * 8 + (lane & 7)) * GPAD + ((lane >> 3) & 1) * 4;

    float acc[4][4][4] = {};

    #define PREFETCH(KT)                                                       \
    do {                                                                       \
        int kt_ = (KT);                                                        \
        if (kt_ < nk) {                                                        \
            int slot_ = kt_ % 3;                                               \
            uint32_t da = sbase + (slot_ * GSTRIDE) * 4;                       \
            uint32_t db = da + GSTG * 4;                                       \
            const uint32_t* Ag_ = A  + (size_t)m0 * Kr + kt_ * GBK;            \
            const uint32_t* Bg_ = Bm + (size_t)n0 * Kr + kt_ * GBK;            \
            _Pragma("unroll")                                                  \
            for (int j = 0; j < 4; j++) {                                      \
                int u = tid + j * 256;                                         \
                int row = u >> 3, c4 = (u & 7) * 4;                            \
                cp16(da + (row * GPAD + c4) * 4, Ag_ + (size_t)row * Kr + c4); \
                cp16(db + (row * GPAD + c4) * 4, Bg_ + (size_t)row * Kr + c4); \
            }                                                                  \
        }                                                                      \
        asm volatile("cp.async.commit_group;");                                \
    } while (0)

    PREFETCH(0);
    PREFETCH(1);

    for (int kt = 0; kt < nk; kt++) {
        asm volatile("cp.async.wait_group 1;");
        __syncthreads();
        PREFETCH(kt + 2);

        const int slot = kt % 3;
        const uint32_t aAddr = sbase + (slot * GSTRIDE) * 4 + (wm0 * GPAD + a_off) * 4;
        const uint32_t bAddr = sbase + (slot * GSTRIDE + GSTG) * 4 + (wn0 * GPAD + b_off) * 4;

        #pragma unroll
        for (int kp = 0; kp < 4; kp++) {
            uint32_t bf[4][2];
            {
                uint32_t r[4];
                ldsm_x4(r, bAddr + kp * 32);
                bf[0][0] = r[0]; bf[0][1] = r[1]; bf[1][0] = r[2]; bf[1][1] = r[3];
            }
            {
                uint32_t r[4];
                ldsm_x4(r, bAddr + 16 * GPAD * 4 + kp * 32);
                bf[2][0] = r[0]; bf[2][1] = r[1]; bf[3][0] = r[2]; bf[3][1] = r[3];
            }
            uint32_t af[4][4];
            #pragma unroll
            for (int mt = 0; mt < 4; mt++)
                ldsm_x4(af[mt], aAddr + mt * 16 * GPAD * 4 + kp * 32);
            #pragma unroll
            for (int mt = 0; mt < 4; mt++)
                #pragma unroll
                for (int nt = 0; nt < 4; nt++)
                    mma_tf32(acc[mt][nt], af[mt], bf[nt]);
        }
    }
    #undef PREFETCH

    if (rnd) {
        #pragma unroll
        for (int mt = 0; mt < 4; mt++)
            #pragma unroll
            for (int nt = 0; nt < 4; nt++)
                #pragma unroll
                for (int e = 0; e < 4; e++)
                    acc[mt][nt][e] = __uint_as_float(f2tf32(acc[mt][nt][e]));
    }
    #pragma unroll
    for (int mt = 0; mt < 4; mt++) {
        #pragma unroll
        for (int nt = 0; nt < 4; nt++) {
            int row = m0 + wm0 + mt*16 + g;
            int col = n0 + wn0 + nt*8 + qc*2;
            float2 lo = make_float2(acc[mt][nt][0], acc[mt][nt][1]);
            float2 hi = make_float2(acc[mt][nt][2], acc[mt][nt][3]);
            *(float2*)(Cm + (size_t)row     * Nr + col) = lo;
            *(float2*)(Cm + (size_t)(row+8) * Nr + col) = hi;
        }
    }
}

// ---------------- gate -----------------------------------------------------
__global__ __launch_bounds__(256)
void gate_kernel(const float* __restrict__ q, const float* __restrict__ gw,
                 const float* __restrict__ gb, float* __restrict__ gate) {
    __shared__ float qrow[C_];
    const int bt = blockIdx.x;
    for (int c = threadIdx.x; c < C_; c += 256)
        qrow[c] = q[(size_t)bt * C_ + c];
    __syncthreads();
    const int warp = threadIdx.x >> 5, lane = threadIdx.x & 31;
    for (int h = warp; h < H_; h += 8) {
        float s = 0.f;
        for (int c = lane; c < C_; c += 32)
            s += qrow[c] * gw[h * C_ + c];
        #pragma unroll
        for (int o = 16; o; o >>= 1) s += __shfl_xor_sync(0xffffffffu, s, o);
        if (lane == 0)
            gate[(size_t)bt * H_ + h] = 1.f / (1.f + __expf(-(s + gb[h])));
    }
}

// ================= attention v3: cp.async + ldmatrix =======================
// CTA: 64 q rows, 4 warps. Smem (words, PAD=68/row):
//   QP[64][68] | K0 | K1 | V0 | V1  (each 64x68). 87040 B, 2 CTA/SM.
// q/k pre-rounded tf32; vT[b][c][s] pre-rounded + transposed.
#define AP 68
#define ATILE (64 * AP)
#define ATT3_SMEM (5 * ATILE * (int)sizeof(uint32_t))

__global__ __launch_bounds__(128, 2)
void attn_tc2(const float* __restrict__ q, const float* __restrict__ k,
              const float* __restrict__ vT, const float* __restrict__ gate,
              float* __restrict__ outp) {
    extern __shared__ uint32_t s3[];
    const uint32_t sbase = (uint32_t)__cvta_generic_to_shared(s3);

    const int tid  = threadIdx.x;
    const int lane = tid & 31, warp = tid >> 5;
    const int g = lane >> 2, qc = lane & 3;
    const int wr0 = warp * 16;
    const int b  = blockIdx.y >> 4;
    const int h  = blockIdx.y & 15;
    const int t0 = (gridDim.x - 1 - blockIdx.x) * 64;

    const int a_off = ((lane & 7) + ((lane >> 3) & 1) * 8) * AP + (lane >> 4) * 4;
    const int b_off = (((lane >> 4) & 1) * 8 + (lane & 7)) * AP + ((lane >> 3) & 1) * 4;

    const int nChunk = t0/64 + 1;
    const int nTiles = nChunk + (2*M_)/64;

    // ---- fill helpers: 64 rows x 64 words, 16-byte chunks ----
    #define FILL_Q()                                                           \
    do {                                                                       \
        const float* src_ = q + ((size_t)(b*T_ + t0)) * C_ + h*HD_;            \
        _Pragma("unroll")                                                      \
        for (int j = 0; j < 8; j++) {                                          \
            int u = tid + j * 128;                                             \
            int row = u >> 4, cw = (u & 15) * 4;                               \
            cp16(sbase + (row * AP + cw) * 4, src_ + (size_t)row * C_ + cw);   \
        }                                                                      \
        asm volatile("cp.async.commit_group;");                                \
    } while (0)

    #define FILL_KV(IT)                                                       \
    do {                                                                      \
        int it_ = (IT);                                                       \
        if (it_ < nTiles) {                                                   \
            int s0_ = (it_ < nChunk) ? it_*64 : T_ + (it_ - nChunk)*64;       \
            int buf_ = it_ & 1;                                               \
            uint32_t kb_ = sbase + ((1 + buf_) * ATILE) * 4;                  \
            uint32_t vb_ = sbase + ((3 + buf_) * ATILE) * 4;                  \
            const float* ks_ = k  + ((size_t)(b*S_ + s0_)) * C_ + h*HD_;      \
            const float* vs_ = vT + ((size_t)(b*C_ + h*HD_)) * S_ + s0_;      \
            _Pragma("unroll")                                                 \
            for (int j = 0; j < 8; j++) {                                     \
                int u = tid + j * 128;                                        \
                int row = u >> 4, cw = (u & 15) * 4;                          \
                cp16(kb_ + (row * AP + cw) * 4, ks_ + (size_t)row * C_ + cw); \
                cp16(vb_ + (row * AP + cw) * 4, vs_ + (size_t)row * S_ + cw); \
            }                                                                 \
        }                                                                     \
        asm volatile("cp.async.commit_group;");                               \
    } while (0)

    FILL_Q();
    FILL_KV(0);
    asm volatile("cp.async.wait_group 1;");   // Q ready
    __syncthreads();

    // ---- Q fragments (scaled by 1/8; exact on tf32 bits) ----
    uint32_t qf[8][4];
    #pragma unroll
    for (int kk = 0; kk < 8; kk++) {
        ldsm_x4(qf[kk], sbase + (wr0 * AP + a_off + kk * 8) * 4);
        #pragma unroll
        for (int e = 0; e < 4; e++)
            qf[kk][e] = __float_as_uint(__uint_as_float(qf[kk][e]) * 0.125f);
    }

    float oc[8][4] = {}, om[8][4] = {};
    float mA = -1e30f, mB = -1e30f, lA = 0.f, lB = 0.f;

    for (int it = 0; it < nTiles; it++) {
        const bool isMem  = (it >= nChunk);
        const int  s0     = isMem ? (T_ + (it - nChunk)*64) : it*64;
        const bool isDiag = (!isMem) && (s0 == t0);
        const uint32_t Kb = sbase + ((1 + (it & 1)) * ATILE) * 4;
        const uint32_t Vb = sbase + ((3 + (it & 1)) * ATILE) * 4;

        FILL_KV(it + 1);
        asm volatile("cp.async.wait_group 1;");   // tile it ready
        __syncthreads();

        // ---- S = Q K^T ----
        float sf[8][4] = {};
        #pragma unroll
        for (int kk = 0; kk < 8; kk++) {
            #pragma unroll
            for (int f2 = 0; f2 < 4; f2++) {
                uint32_t r[4];
                ldsm_x4(r, Kb + (f2 * 16 * AP + b_off + kk * 8) * 4);
                uint32_t b0[2] = {r[0], r[1]}, b1[2] = {r[2], r[3]};
                mma_tf32(sf[2*f2],     qf[kk], b0);
                mma_tf32(sf[2*f2 + 1], qf[kk], b1);
            }
        }

        // ---- mask + row max ----
        float tmA = -1e30f, tmB = -1e30f;
        #pragma unroll
        for (int f = 0; f < 8; f++) {
            if (isDiag) {
                int c0 = f*8 + 2*qc, c1 = c0 + 1;
                int rA = wr0 + g, rB = rA + 8;
                if (c0 > rA) sf[f][0] = -1e30f;
                if (c1 > rA) sf[f][1] = -1e30f;
                if (c0 > rB) sf[f][2] = -1e30f;
                if (c1 > rB) sf[f][3] = -1e30f;
            }
            tmA = fmaxf(tmA, fmaxf(sf[f][0], sf[f][1]));
            tmB = fmaxf(tmB, fmaxf(sf[f][2], sf[f][3]));
        }
        tmA = fmaxf(tmA, __shfl_xor_sync(~0u, tmA, 1));
        tmA = fmaxf(tmA, __shfl_xor_sync(~0u, tmA, 2));
        tmB = fmaxf(tmB, __shfl_xor_sync(~0u, tmB, 1));
        tmB = fmaxf(tmB, __shfl_xor_sync(~0u, tmB, 2));

        float mAn = fmaxf(mA, tmA), mBn = fmaxf(mB, tmB);
        float fA = __expf(mA - mAn), fB = __expf(mB - mBn);
        mA = mAn; mB = mBn;

        // ---- P = exp(S-m) -> smem (QP buffer), row sums ----
        float sA = 0.f, sB = 0.f;
        #pragma unroll
        for (int f = 0; f < 8; f++) {
            float p0 = __expf(sf[f][0] - mA);
            float p1 = __expf(sf[f][1] - mA);
            float p2 = __expf(sf[f][2] - mB);
            float p3 = __expf(sf[f][3] - mB);
            sA += p0 + p1; sB += p2 + p3;
            uint2 lo = make_uint2(f2tf32(p0), f2tf32(p1));
            uint2 hi = make_uint2(f2tf32(p2), f2tf32(p3));
            *(uint2*)&s3[(wr0 + g    )*AP + f*8 + 2*qc] = lo;
            *(uint2*)&s3[(wr0 + g + 8)*AP + f*8 + 2*qc] = hi;
        }
        sA += __shfl_xor_sync(~0u, sA, 1); sA += __shfl_xor_sync(~0u, sA, 2);
        sB += __shfl_xor_sync(~0u, sB, 1); sB += __shfl_xor_sync(~0u, sB, 2);
        lA = lA * fA + sA;
        lB = lB * fB + sB;

        // ---- rescale accumulators ----
        #pragma unroll
        for (int f = 0; f < 8; f++) {
            oc[f][0] *= fA; oc[f][1] *= fA; oc[f][2] *= fB; oc[f][3] *= fB;
            om[f][0] *= fA; om[f][1] *= fA; om[f][2] *= fB; om[f][3] *= fB;
        }
        __syncwarp();

        // ---- P fragments (A operand) ----
        uint32_t pf[8][4];
        #pragma unroll
        for (int kk = 0; kk < 8; kk++)
            ldsm_x4(pf[kk], sbase + (wr0 * AP + a_off + kk * 8) * 4);

        // ---- O += P V ----
        float (*accp)[4] = isMem ? om : oc;
        #pragma unroll
        for (int kk = 0; kk < 8; kk++) {
            #pragma unroll
            for (int f2 = 0; f2 < 4; f2++) {
                uint32_t r[4];
                ldsm_x4(r, Vb + (f2 * 16 * AP + b_off + kk * 8) * 4);
                uint32_t b0[2] = {r[0], r[1]}, b1[2] = {r[2], r[3]};
                mma_tf32(accp[2*f2],     pf[kk], b0);
                mma_tf32(accp[2*f2 + 1], pf[kk], b1);
            }
        }
        __syncthreads();   // all warps done with K/V bufs before refill
    }
    #undef FILL_Q
    #undef FILL_KV

    // ---- epilogue ----
    int rA = t0 + wr0 + g, rB = rA + 8;
    float gA = gate[(size_t)(b*T_ + rA) * H_ + h];
    float gB = gate[(size_t)(b*T_ + rB) * H_ + h];
    float invA = 1.f / lA, invB = 1.f / lB;
    #pragma unroll
    for (int f = 0; f < 8; f++) {
        int col = h*HD_ + f*8 + 2*qc;
        float2 o0 = make_float2((oc[f][0] + gA*om[f][0]) * invA,
                                (oc[f][1] + gA*om[f][1]) * invA);
        float2 o1 = make_float2((oc[f][2] + gB*om[f][2]) * invB,
                                (oc[f][3] + gB*om[f][3]) * invB);
        *(float2*)&outp[(size_t)(b*T_ + rA) * C_ + col] = o0;
        *(float2*)&outp[(size_t)(b*T_ + rB) * C_ + col] = o1;
    }
}

// ---------------- canon conv -> tf32 bits ----------------------------------
__global__ __launch_bounds__(256)
void conv_kernel(const float* __restrict__ y, const float* __restrict__ cw,
                 const float* __restrict__ cb, uint32_t* __restrict__ z) {
    int idx = blockIdx.x * 256 + threadIdx.x;
    if (idx >= B_*T_*C_) return;
    int c = idx % C_;
    int t = (idx / C_) % T_;
    int b = idx / (C_ * T_);
    float s = y[idx] + cb[c];
    #pragma unroll
    for (int j = 0; j < KC_; j++) {
        int tt = t - (KC_ - 1) + j;
        if (tt >= 0)
            s += y[((size_t)(b*T_ + tt)) * C_ + c] * cw[c*KC_ + j];
    }
    z[idx] = f2tf32(s);
}

// ---------------- orchestration -------------------------------------------
extern "C" void kernel_launch(void* const* d_in, const int* in_sizes, int n_in,
                              void* d_out, int out_size) {
    const float* x   = (const float*)d_in[0];
    const float* fwd = (const float*)d_in[1];
    const float* rev = (const float*)d_in[2];
    const float* Wq  = (const float*)d_in[3];
    const float* Wk  = (const float*)d_in[4];
    const float* Wv  = (const float*)d_in[5];
    const float* Wo  = (const float*)d_in[6];
    const float* gw  = (const float*)d_in[7];
    const float* gb  = (const float*)d_in[8];
    const float* cw  = (const float*)d_in[9];
    const float* cb  = (const float*)d_in[10];
    float* out = (float*)d_out;

    uint32_t *xc, *xtf, *wtf, *ztf;
    float *qb, *kb, *vb, *vt, *gt, *at;
    cudaGetSymbolAddress((void**)&xc,  g_xcat);
    cudaGetSymbolAddress((void**)&xtf, g_xtf);
    cudaGetSymbolAddress((void**)&wtf, g_wtf);
    cudaGetSymbolAddress((void**)&ztf, g_ztf);
    cudaGetSymbolAddress((void**)&qb,  g_q);
    cudaGetSymbolAddress((void**)&kb,  g_k);
    cudaGetSymbolAddress((void**)&vb,  g_v);
    cudaGetSymbolAddress((void**)&vt,  g_vt);
    cudaGetSymbolAddress((void**)&gt,  g_gate);
    cudaGetSymbolAddress((void**)&at,  g_attn);

    cudaFuncSetAttribute(gemm_tc,
                         cudaFuncAttributeMaxDynamicSharedMemorySize, GEMM2_SMEM);
    cudaFuncSetAttribute(attn_tc2,
                         cudaFuncAttributeMaxDynamicSharedMemorySize, ATT3_SMEM);

    // 1. pre-convert inputs
    {
        int n4 = B_*S_*(C_/4);
        pack_kernel<<<(n4 + 255)/256, 256>>>((const float4*)x, (const float4*)fwd,
                                             (const float4*)rev, (uint4*)xc);
    }
    wcvt_kernel<<<(4*C_*C_/4 + 255)/256, 256>>>((const float4*)Wq, (const float4*)Wk,
                                                (const float4*)Wv, (const float4*)Wo,
                                                (uint4*)wtf);
    xcvt_kernel<<<(B_*T_*C_/4 + 255)/256, 256>>>((const float4*)x, (uint4*)xtf,
                                                 B_*T_*C_/4);

    // 2. projections (outputs tf32-rounded)
    gemm_tc<<<dim3(C_/128, (B_*T_)/128), 256, GEMM2_SMEM>>>(xtf, wtf,           qb, B_*T_, C_, C_, 1);
    gemm_tc<<<dim3(C_/128, (B_*S_)/128), 256, GEMM2_SMEM>>>(xc,  wtf + C_*C_,   kb, B_*S_, C_, C_, 1);
    gemm_tc<<<dim3(C_/128, (B_*S_)/128), 256, GEMM2_SMEM>>>(xc,  wtf + 2*C_*C_, vb, B_*S_, C_, C_, 1);
    // 3. V transpose + gate
    vtrans_kernel<<<dim3(S_/32, C_/32, B_), 256>>>(vb, vt);
    gate_kernel<<<B_*T_, 256>>>(qb, gw, gb, gt);
    // 4. attention
    attn_tc2<<<dim3(T_/64, B_*H_), 128, ATT3_SMEM>>>(qb, kb, vt, gt, at);
    // 5. canon conv (writes tf32)
    conv_kernel<<<(B_*T_*C_ + 255)/256, 256>>>(at, cw, cb, ztf);
    // 6. output projection into d_out (plain fp32 out)
    gemm_tc<<<dim3(C_/128, (B_*T_)/128), 256, GEMM2_SMEM>>>(ztf, wtf + 3*C_*C_, out, B_*T_, C_, C_, 0);
}

// round 6
// speedup vs baseline: 4.2618x; 1.1034x over previous
#include <cuda_runtime.h>
#include <math.h>
#include <stdint.h>

#define B_ 2
#define T_ 2048
#define C_ 1024
#define H_ 16
#define HD_ 64
#define M_ 256
#define S_ (T_ + 2*M_)   /* 2560 */
#define KC_ 4

// ---------------- scratch (static device globals; no runtime alloc) -------
__device__ uint32_t g_xcat[B_*S_*C_];   // concat(x,fwd,rev) as tf32 bits
__device__ uint32_t g_wtf [4*C_*C_];    // Wq|Wk|Wv|Wo as tf32 bits
__device__ float    g_q   [B_*T_*C_];   // tf32-rounded
__device__ float    g_k   [B_*S_*C_];   // tf32-rounded
__device__ float    g_v   [B_*S_*C_];   // tf32-rounded
__device__ float    g_vt  [B_*C_*S_];   // V transposed per (b,c): [b][c][s]
__device__ float    g_gate[B_*T_*H_];
__device__ float    g_attn[B_*T_*C_];
__device__ uint32_t g_ztf [B_*T_*C_];   // conv output as tf32 bits

// ================= TF32 helpers ===========================================
__device__ __forceinline__ uint32_t f2tf32(float f) {
    uint32_t r;
    asm("cvt.rna.tf32.f32 %0, %1;" : "=r"(r) : "f"(f));
    return r;
}
__device__ __forceinline__ void mma_tf32(float* d, const uint32_t* a,
                                         const uint32_t* b) {
    asm volatile(
        "mma.sync.aligned.m16n8k8.row.col.f32.tf32.tf32.f32 "
        "{%0,%1,%2,%3}, {%4,%5,%6,%7}, {%8,%9}, {%0,%1,%2,%3};"
        : "+f"(d[0]), "+f"(d[1]), "+f"(d[2]), "+f"(d[3])
        : "r"(a[0]), "r"(a[1]), "r"(a[2]), "r"(a[3]),
          "r"(b[0]), "r"(b[1]));
}
__device__ __forceinline__ void ldsm_x4(uint32_t* r, uint32_t addr) {
    asm volatile("ldmatrix.sync.aligned.m8n8.x4.shared.b16 {%0,%1,%2,%3}, [%4];"
        : "=r"(r[0]), "=r"(r[1]), "=r"(r[2]), "=r"(r[3]) : "r"(addr));
}
__device__ __forceinline__ void cp16(uint32_t dst, const void* src) {
    asm volatile("cp.async.cg.shared.global [%0], [%1], 16;" :: "r"(dst), "l"(src));
}

// ---------------- pack: xcat = concat(x, fwd, rev) -> tf32 bits ----------
__global__ void pack_kernel(const float4* __restrict__ x,
                            const float4* __restrict__ fwd,
                            const float4* __restrict__ rev,
                            uint4* __restrict__ xc) {
    const int C4 = C_/4;
    int idx = blockIdx.x * 256 + threadIdx.x;
    if (idx >= B_*S_*C4) return;
    int c4 = idx % C4;
    int r  = (idx / C4) % S_;
    int b  = idx / (C4 * S_);
    float4 val;
    if (r < T_)            val = x  [(b*T_ + r)          * C4 + c4];
    else if (r < T_ + M_)  val = fwd[(b*M_ + (r - T_))   * C4 + c4];
    else                   val = rev[(b*M_ + (r - T_-M_))* C4 + c4];
    xc[idx] = make_uint4(f2tf32(val.x), f2tf32(val.y), f2tf32(val.z), f2tf32(val.w));
}

// ---------------- weight cvt ------------------------------------------------
__global__ void wcvt_kernel(const float4* __restrict__ w0, const float4* __restrict__ w1,
                            const float4* __restrict__ w2, const float4* __restrict__ w3,
                            uint4* __restrict__ dst) {
    const int n4 = C_*C_/4;
    int idx = blockIdx.x * 256 + threadIdx.x;
    if (idx >= 4*n4) return;
    int m = idx / n4, r = idx % n4;
    const float4* s = (m == 0) ? w0 : (m == 1) ? w1 : (m == 2) ? w2 : w3;
    float4 v = s[r];
    dst[idx] = make_uint4(f2tf32(v.x), f2tf32(v.y), f2tf32(v.z), f2tf32(v.w));
}

// ---------------- V transpose: vT[b][c][s] = v[b][s][c] --------------------
__global__ __launch_bounds__(256)
void vtrans_kernel(const float* __restrict__ v, float* __restrict__ vT) {
    __shared__ float tile[32][33];
    const int tx = threadIdx.x & 31, ty = threadIdx.x >> 5;  // 32 x 8
    const int s0 = blockIdx.x * 32, c0 = blockIdx.y * 32, b = blockIdx.z;
    #pragma unroll
    for (int i = 0; i < 4; i++)
        tile[ty + i*8][tx] = v[((size_t)(b*S_ + s0 + ty + i*8)) * C_ + c0 + tx];
    __syncthreads();
    #pragma unroll
    for (int i = 0; i < 4; i++)
        vT[((size_t)(b*C_ + c0 + ty + i*8)) * S_ + s0 + tx] = tile[tx][ty + i*8];
}

// ================= TF32 GEMM: cp.async 3-stage + ldmatrix ==================
// mode 0: C[m,n] -> Cm (ld Nr), optional tf32 rounding (rnd)
// mode 1: fused QKV routing: n<1024 -> qp (rows r<T only), <2048 -> kp, else vp
#define GBM 128
#define GBN 128
#define GBK 32
#define GPAD 36
#define GSTG (GBM * GPAD)
#define GSTRIDE (2 * GSTG)
#define GEMM2_SMEM (3 * GSTRIDE * (int)sizeof(uint32_t))

__global__ __launch_bounds__(256)
void gemm_tc(const uint32_t* __restrict__ A, const uint32_t* __restrict__ Bm,
             float* __restrict__ Cm, float* __restrict__ qp,
             float* __restrict__ kp, float* __restrict__ vp,
             int Mr, int Nr, int Kr, int rnd, int mode) {
    // fused mode: skip CTAs that would compute q columns for memory rows
    if (mode == 1 && blockIdx.x < 8 && (blockIdx.y % 20) >= 16) return;

    extern __shared__ uint32_t smg[];
    const uint32_t sbase = (uint32_t)__cvta_generic_to_shared(smg);

    const int tid  = threadIdx.x;
    const int lane = tid & 31, warp = tid >> 5;
    const int g = lane >> 2, qc = lane & 3;
    const int wm0 = (warp >> 2) * 64;
    const int wn0 = (warp & 3) * 32;
    const int m0 = blockIdx.y * GBM, n0 = blockIdx.x * GBN;
    const int nk = Kr / GBK;

    const int a_off = ((lane & 7) + ((lane >> 3) & 1) * 8) * GPAD + (lane >> 4) * 4;
    const int b_off = (((lane >> 4) & 1) * 8 + (lane & 7)) * GPAD + ((lane >> 3) & 1) * 4;

    float acc[4][4][4] = {};

    #define PREFETCH(KT)                                                       \
    do {                                                                       \
        int kt_ = (KT);                                                        \
        if (kt_ < nk) {                                                        \
            int slot_ = kt_ % 3;                                               \
            uint32_t da = sbase + (slot_ * GSTRIDE) * 4;                       \
            uint32_t db = da + GSTG * 4;                                       \
            const uint32_t* Ag_ = A  + (size_t)m0 * Kr + kt_ * GBK;            \
            const uint32_t* Bg_ = Bm + (size_t)n0 * Kr + kt_ * GBK;            \
            _Pragma("unroll")                                                  \
            for (int j = 0; j < 4; j++) {                                      \
                int u = tid + j * 256;                                         \
                int row = u >> 3, c4 = (u & 7) * 4;                            \
                cp16(da + (row * GPAD + c4) * 4, Ag_ + (size_t)row * Kr + c4); \
                cp16(db + (row * GPAD + c4) * 4, Bg_ + (size_t)row * Kr + c4); \
            }                                                                  \
        }                                                                      \
        asm volatile("cp.async.commit_group;");                                \
    } while (0)

    PREFETCH(0);
    PREFETCH(1);

    for (int kt = 0; kt < nk; kt++) {
        asm volatile("cp.async.wait_group 1;");
        __syncthreads();
        PREFETCH(kt + 2);

        const int slot = kt % 3;
        const uint32_t aAddr = sbase + (slot * GSTRIDE) * 4 + (wm0 * GPAD + a_off) * 4;
        const uint32_t bAddr = sbase + (slot * GSTRIDE + GSTG) * 4 + (wn0 * GPAD + b_off) * 4;

        #pragma unroll
        for (int kp_ = 0; kp_ < 4; kp_++) {
            uint32_t bf[4][2];
            {
                uint32_t r[4];
                ldsm_x4(r, bAddr + kp_ * 32);
                bf[0][0] = r[0]; bf[0][1] = r[1]; bf[1][0] = r[2]; bf[1][1] = r[3];
            }
            {
                uint32_t r[4];
                ldsm_x4(r, bAddr + 16 * GPAD * 4 + kp_ * 32);
                bf[2][0] = r[0]; bf[2][1] = r[1]; bf[3][0] = r[2]; bf[3][1] = r[3];
            }
            uint32_t af[4][4];
            #pragma unroll
            for (int mt = 0; mt < 4; mt++)
                ldsm_x4(af[mt], aAddr + mt * 16 * GPAD * 4 + kp_ * 32);
            #pragma unroll
            for (int mt = 0; mt < 4; mt++)
                #pragma unroll
                for (int nt = 0; nt < 4; nt++)
                    mma_tf32(acc[mt][nt], af[mt], bf[nt]);
        }
    }
    #undef PREFETCH

    if (rnd) {
        #pragma unroll
        for (int mt = 0; mt < 4; mt++)
            #pragma unroll
            for (int nt = 0; nt < 4; nt++)
                #pragma unroll
                for (int e = 0; e < 4; e++)
                    acc[mt][nt][e] = __uint_as_float(f2tf32(acc[mt][nt][e]));
    }

    if (mode == 0) {
        #pragma unroll
        for (int mt = 0; mt < 4; mt++) {
            #pragma unroll
            for (int nt = 0; nt < 4; nt++) {
                int row = m0 + wm0 + mt*16 + g;
                int col = n0 + wn0 + nt*8 + qc*2;
                float2 lo = make_float2(acc[mt][nt][0], acc[mt][nt][1]);
                float2 hi = make_float2(acc[mt][nt][2], acc[mt][nt][3]);
                *(float2*)(Cm + (size_t)row     * Nr + col) = lo;
                *(float2*)(Cm + (size_t)(row+8) * Nr + col) = hi;
            }
        }
    } else {
        #pragma unroll
        for (int mt = 0; mt < 4; mt++) {
            #pragma unroll
            for (int nt = 0; nt < 4; nt++) {
                int row = m0 + wm0 + mt*16 + g;          // 0..B*S-1
                int col = n0 + wn0 + nt*8 + qc*2;        // 0..3071
                int which = col >> 10, lc = col & 1023;
                int bb = row / S_, rr = row % S_;        // rr,rr+8 same side of T_
                float2 lo = make_float2(acc[mt][nt][0], acc[mt][nt][1]);
                float2 hi = make_float2(acc[mt][nt][2], acc[mt][nt][3]);
                if (which == 0) {
                    if (rr < T_) {
                        float* dst = qp + ((size_t)(bb*T_ + rr)) * C_ + lc;
                        *(float2*)(dst)         = lo;
                        *(float2*)(dst + 8*C_)  = hi;
                    }
                } else {
                    float* dst = ((which == 1) ? kp : vp) + (size_t)row * C_ + lc;
                    *(float2*)(dst)         = lo;
                    *(float2*)(dst + 8*C_)  = hi;
                }
            }
        }
    }
}

// ---------------- gate -----------------------------------------------------
__global__ __launch_bounds__(256)
void gate_kernel(const float* __restrict__ q, const float* __restrict__ gw,
                 const float* __restrict__ gb, float* __restrict__ gate) {
    __shared__ float qrow[C_];
    const int bt = blockIdx.x;
    for (int c = threadIdx.x; c < C_; c += 256)
        qrow[c] = q[(size_t)bt * C_ + c];
    __syncthreads();
    const int warp = threadIdx.x >> 5, lane = threadIdx.x & 31;
    for (int h = warp; h < H_; h += 8) {
        float s = 0.f;
        for (int c = lane; c < C_; c += 32)
            s += qrow[c] * gw[h * C_ + c];
        #pragma unroll
        for (int o = 16; o; o >>= 1) s += __shfl_xor_sync(0xffffffffu, s, o);
        if (lane == 0)
            gate[(size_t)bt * H_ + h] = 1.f / (1.f + __expf(-(s + gb[h])));
    }
}

// ================= attention: cp.async + ldmatrix ==========================
#define AP 68
#define ATILE (64 * AP)
#define ATT3_SMEM (5 * ATILE * (int)sizeof(uint32_t))

__global__ __launch_bounds__(128, 2)
void attn_tc2(const float* __restrict__ q, const float* __restrict__ k,
              const float* __restrict__ vT, const float* __restrict__ gate,
              float* __restrict__ outp) {
    extern __shared__ uint32_t s3[];
    const uint32_t sbase = (uint32_t)__cvta_generic_to_shared(s3);

    const int tid  = threadIdx.x;
    const int lane = tid & 31, warp = tid >> 5;
    const int g = lane >> 2, qc = lane & 3;
    const int wr0 = warp * 16;
    const int b  = blockIdx.y >> 4;
    const int h  = blockIdx.y & 15;
    const int t0 = (gridDim.x - 1 - blockIdx.x) * 64;

    const int a_off = ((lane & 7) + ((lane >> 3) & 1) * 8) * AP + (lane >> 4) * 4;
    const int b_off = (((lane >> 4) & 1) * 8 + (lane & 7)) * AP + ((lane >> 3) & 1) * 4;

    const int nChunk = t0/64 + 1;
    const int nTiles = nChunk + (2*M_)/64;

    #define FILL_Q()                                                           \
    do {                                                                       \
        const float* src_ = q + ((size_t)(b*T_ + t0)) * C_ + h*HD_;            \
        _Pragma("unroll")                                                      \
        for (int j = 0; j < 8; j++) {                                          \
            int u = tid + j * 128;                                             \
            int row = u >> 4, cw = (u & 15) * 4;                               \
            cp16(sbase + (row * AP + cw) * 4, src_ + (size_t)row * C_ + cw);   \
        }                                                                      \
        asm volatile("cp.async.commit_group;");                                \
    } while (0)

    #define FILL_KV(IT)                                                       \
    do {                                                                      \
        int it_ = (IT);                                                       \
        if (it_ < nTiles) {                                                   \
            int s0_ = (it_ < nChunk) ? it_*64 : T_ + (it_ - nChunk)*64;       \
            int buf_ = it_ & 1;                                               \
            uint32_t kb_ = sbase + ((1 + buf_) * ATILE) * 4;                  \
            uint32_t vb_ = sbase + ((3 + buf_) * ATILE) * 4;                  \
            const float* ks_ = k  + ((size_t)(b*S_ + s0_)) * C_ + h*HD_;      \
            const float* vs_ = vT + ((size_t)(b*C_ + h*HD_)) * S_ + s0_;      \
            _Pragma("unroll")                                                 \
            for (int j = 0; j < 8; j++) {                                     \
                int u = tid + j * 128;                                        \
                int row = u >> 4, cw = (u & 15) * 4;                          \
                cp16(kb_ + (row * AP + cw) * 4, ks_ + (size_t)row * C_ + cw); \
                cp16(vb_ + (row * AP + cw) * 4, vs_ + (size_t)row * S_ + cw); \
            }                                                                 \
        }                                                                     \
        asm volatile("cp.async.commit_group;");                               \
    } while (0)

    FILL_Q();
    FILL_KV(0);
    asm volatile("cp.async.wait_group 1;");
    __syncthreads();

    uint32_t qf[8][4];
    #pragma unroll
    for (int kk = 0; kk < 8; kk++) {
        ldsm_x4(qf[kk], sbase + (wr0 * AP + a_off + kk * 8) * 4);
        #pragma unroll
        for (int e = 0; e < 4; e++)
            qf[kk][e] = __float_as_uint(__uint_as_float(qf[kk][e]) * 0.125f);
    }

    float oc[8][4] = {}, om[8][4] = {};
    float mA = -1e30f, mB = -1e30f, lA = 0.f, lB = 0.f;

    for (int it = 0; it < nTiles; it++) {
        const bool isMem  = (it >= nChunk);
        const int  s0     = isMem ? (T_ + (it - nChunk)*64) : it*64;
        const bool isDiag = (!isMem) && (s0 == t0);
        const uint32_t Kb = sbase + ((1 + (it & 1)) * ATILE) * 4;
        const uint32_t Vb = sbase + ((3 + (it & 1)) * ATILE) * 4;

        FILL_KV(it + 1);
        asm volatile("cp.async.wait_group 1;");
        __syncthreads();

        float sf[8][4] = {};
        #pragma unroll
        for (int kk = 0; kk < 8; kk++) {
            #pragma unroll
            for (int f2 = 0; f2 < 4; f2++) {
                uint32_t r[4];
                ldsm_x4(r, Kb + (f2 * 16 * AP + b_off + kk * 8) * 4);
                uint32_t b0[2] = {r[0], r[1]}, b1[2] = {r[2], r[3]};
                mma_tf32(sf[2*f2],     qf[kk], b0);
                mma_tf32(sf[2*f2 + 1], qf[kk], b1);
            }
        }

        float tmA = -1e30f, tmB = -1e30f;
        #pragma unroll
        for (int f = 0; f < 8; f++) {
            if (isDiag) {
                int c0 = f*8 + 2*qc, c1 = c0 + 1;
                int rA = wr0 + g, rB = rA + 8;
                if (c0 > rA) sf[f][0] = -1e30f;
                if (c1 > rA) sf[f][1] = -1e30f;
                if (c0 > rB) sf[f][2] = -1e30f;
                if (c1 > rB) sf[f][3] = -1e30f;
            }
            tmA = fmaxf(tmA, fmaxf(sf[f][0], sf[f][1]));
            tmB = fmaxf(tmB, fmaxf(sf[f][2], sf[f][3]));
        }
        tmA = fmaxf(tmA, __shfl_xor_sync(~0u, tmA, 1));
        tmA = fmaxf(tmA, __shfl_xor_sync(~0u, tmA, 2));
        tmB = fmaxf(tmB, __shfl_xor_sync(~0u, tmB, 1));
        tmB = fmaxf(tmB, __shfl_xor_sync(~0u, tmB, 2));

        float mAn = fmaxf(mA, tmA), mBn = fmaxf(mB, tmB);
        float fA = __expf(mA - mAn), fB = __expf(mB - mBn);
        mA = mAn; mB = mBn;

        float sA = 0.f, sB = 0.f;
        #pragma unroll
        for (int f = 0; f < 8; f++) {
            float p0 = __expf(sf[f][0] - mA);
            float p1 = __expf(sf[f][1] - mA);
            float p2 = __expf(sf[f][2] - mB);
            float p3 = __expf(sf[f][3] - mB);
            sA += p0 + p1; sB += p2 + p3;
            uint2 lo = make_uint2(f2tf32(p0), f2tf32(p1));
            uint2 hi = make_uint2(f2tf32(p2), f2tf32(p3));
            *(uint2*)&s3[(wr0 + g    )*AP + f*8 + 2*qc] = lo;
            *(uint2*)&s3[(wr0 + g + 8)*AP + f*8 + 2*qc] = hi;
        }
        sA += __shfl_xor_sync(~0u, sA, 1); sA += __shfl_xor_sync(~0u, sA, 2);
        sB += __shfl_xor_sync(~0u, sB, 1); sB += __shfl_xor_sync(~0u, sB, 2);
        lA = lA * fA + sA;
        lB = lB * fB + sB;

        #pragma unroll
        for (int f = 0; f < 8; f++) {
            oc[f][0] *= fA; oc[f][1] *= fA; oc[f][2] *= fB; oc[f][3] *= fB;
            om[f][0] *= fA; om[f][1] *= fA; om[f][2] *= fB; om[f][3] *= fB;
        }
        __syncwarp();

        uint32_t pf[8][4];
        #pragma unroll
        for (int kk = 0; kk < 8; kk++)
            ldsm_x4(pf[kk], sbase + (wr0 * AP + a_off + kk * 8) * 4);

        float (*accp)[4] = isMem ? om : oc;
        #pragma unroll
        for (int kk = 0; kk < 8; kk++) {
            #pragma unroll
            for (int f2 = 0; f2 < 4; f2++) {
                uint32_t r[4];
                ldsm_x4(r, Vb + (f2 * 16 * AP + b_off + kk * 8) * 4);
                uint32_t b0[2] = {r[0], r[1]}, b1[2] = {r[2], r[3]};
                mma_tf32(accp[2*f2],     pf[kk], b0);
                mma_tf32(accp[2*f2 + 1], pf[kk], b1);
            }
        }
        __syncthreads();
    }
    #undef FILL_Q
    #undef FILL_KV

    int rA = t0 + wr0 + g, rB = rA + 8;
    float gA = gate[(size_t)(b*T_ + rA) * H_ + h];
    float gB = gate[(size_t)(b*T_ + rB) * H_ + h];
    float invA = 1.f / lA, invB = 1.f / lB;
    #pragma unroll
    for (int f = 0; f < 8; f++) {
        int col = h*HD_ + f*8 + 2*qc;
        float2 o0 = make_float2((oc[f][0] + gA*om[f][0]) * invA,
                                (oc[f][1] + gA*om[f][1]) * invA);
        float2 o1 = make_float2((oc[f][2] + gB*om[f][2]) * invB,
                                (oc[f][3] + gB*om[f][3]) * invB);
        *(float2*)&outp[(size_t)(b*T_ + rA) * C_ + col] = o0;
        *(float2*)&outp[(size_t)(b*T_ + rB) * C_ + col] = o1;
    }
}

// ---------------- canon conv -> tf32 bits ----------------------------------
__global__ __launch_bounds__(256)
void conv_kernel(const float* __restrict__ y, const float* __restrict__ cw,
                 const float* __restrict__ cb, uint32_t* __restrict__ z) {
    int idx = blockIdx.x * 256 + threadIdx.x;
    if (idx >= B_*T_*C_) return;
    int c = idx % C_;
    int t = (idx / C_) % T_;
    int b = idx / (C_ * T_);
    float s = y[idx] + cb[c];
    #pragma unroll
    for (int j = 0; j < KC_; j++) {
        int tt = t - (KC_ - 1) + j;
        if (tt >= 0)
            s += y[((size_t)(b*T_ + tt)) * C_ + c] * cw[c*KC_ + j];
    }
    z[idx] = f2tf32(s);
}

// ---------------- orchestration -------------------------------------------
extern "C" void kernel_launch(void* const* d_in, const int* in_sizes, int n_in,
                              void* d_out, int out_size) {
    const float* x   = (const float*)d_in[0];
    const float* fwd = (const float*)d_in[1];
    const float* rev = (const float*)d_in[2];
    const float* Wq  = (const float*)d_in[3];
    const float* Wk  = (const float*)d_in[4];
    const float* Wv  = (const float*)d_in[5];
    const float* Wo  = (const float*)d_in[6];
    const float* gw  = (const float*)d_in[7];
    const float* gb  = (const float*)d_in[8];
    const float* cw  = (const float*)d_in[9];
    const float* cb  = (const float*)d_in[10];
    float* out = (float*)d_out;

    uint32_t *xc, *wtf, *ztf;
    float *qb, *kb, *vb, *vt, *gt, *at;
    cudaGetSymbolAddress((void**)&xc,  g_xcat);
    cudaGetSymbolAddress((void**)&wtf, g_wtf);
    cudaGetSymbolAddress((void**)&ztf, g_ztf);
    cudaGetSymbolAddress((void**)&qb,  g_q);
    cudaGetSymbolAddress((void**)&kb,  g_k);
    cudaGetSymbolAddress((void**)&vb,  g_v);
    cudaGetSymbolAddress((void**)&vt,  g_vt);
    cudaGetSymbolAddress((void**)&gt,  g_gate);
    cudaGetSymbolAddress((void**)&at,  g_attn);

    cudaFuncSetAttribute(gemm_tc,
                         cudaFuncAttributeMaxDynamicSharedMemorySize, GEMM2_SMEM);
    cudaFuncSetAttribute(attn_tc2,
                         cudaFuncAttributeMaxDynamicSharedMemorySize, ATT3_SMEM);

    // 1. pre-convert inputs
    {
        int n4 = B_*S_*(C_/4);
        pack_kernel<<<(n4 + 255)/256, 256>>>((const float4*)x, (const float4*)fwd,
                                             (const float4*)rev, (uint4*)xc);
    }
    wcvt_kernel<<<(4*C_*C_/4 + 255)/256, 256>>>((const float4*)Wq, (const float4*)Wk,
                                                (const float4*)Wv, (const float4*)Wo,
                                                (uint4*)wtf);

    // 2. fused QKV projection: A=xcat (B*S x C), B=[Wq|Wk|Wv] (3072 x C)
    gemm_tc<<<dim3(3*C_/128, (B_*S_)/128), 256, GEMM2_SMEM>>>(
        xc, wtf, nullptr, qb, kb, vb, B_*S_, 3*C_, C_, 1, 1);

    // 3. V transpose + gate
    vtrans_kernel<<<dim3(S_/32, C_/32, B_), 256>>>(vb, vt);
    gate_kernel<<<B_*T_, 256>>>(qb, gw, gb, gt);
    // 4. attention
    attn_tc2<<<dim3(T_/64, B_*H_), 128, ATT3_SMEM>>>(qb, kb, vt, gt, at);
    // 5. canon conv (writes tf32)
    conv_kernel<<<(B_*T_*C_ + 255)/256, 256>>>(at, cw, cb, ztf);
    // 6. output projection into d_out
    gemm_tc<<<dim3(C_/128, (B_*T_)/128), 256, GEMM2_SMEM>>>(
        ztf, wtf + 3*C_*C_, out, nullptr, nullptr, nullptr, B_*T_, C_, C_, 0, 0);
}